// round 2
// baseline (speedup 1.0000x reference)
#include <cuda_runtime.h>
#include <math.h>

// ---------------- problem constants ----------------
#define BATCH    8
#define LSEQ     1024
#define DMODEL   512
#define DINNER   1024     // 2*DMODEL
#define DSTATE   32
#define DCONV    4
#define DTRANK   32
#define NLAYERS  2
#define NMELS    128
#define NCLASSES 1251
#define NTOK     (BATCH*LSEQ)      // 8192
#define DBCW     (DTRANK + 2*DSTATE) // 96

// ---------------- scratch (__device__ globals; no allocs allowed) ----------------
__device__ float g_h    [NTOK * DMODEL];        // residual stream
__device__ float g_xz   [NTOK * 2 * DINNER];    // in_proj output (xm | res)
__device__ float g_xc   [NTOK * DINNER];        // conv+silu output (u)
__device__ float g_dbc  [NTOK * DBCW];          // x_proj output (dt | B | C)
__device__ float g_delta[NTOK * DINNER];        // softplus(dt@Wdt + bdt)
__device__ float g_y    [NTOK * DINNER];        // gated scan output
__device__ float g_gout [NTOK * DMODEL];        // out_proj output (pre-LN)
__device__ float g_A2   [NLAYERS * DINNER * DSTATE]; // A * log2(e)
__device__ float g_pool [BATCH * DMODEL];

// ---------------- helpers ----------------
__device__ __forceinline__ float ex2f(float x) {
    float y; asm("ex2.approx.ftz.f32 %0, %1;" : "=f"(y) : "f"(x)); return y;
}
__device__ __forceinline__ float softplus_f(float x) {
    return (x > 20.f) ? x : log1pf(expf(x));
}
__device__ __forceinline__ float silu_f(float x) {
    return x / (1.f + expf(-x));
}

// ---------------- generic fp32 GEMM: C[M,N] = A[M,K] @ W[N,K]^T (+bias)(+softplus) ----
// BM=128 BN=64 BK=16, 256 threads, 8x4 microtile. M must be multiple of 128,
// K multiple of 16; N guarded (must be multiple of 4).
// EPI: 0=none, 1=+bias[n], 2=softplus(acc + bias[n])
template<int EPI>
__global__ __launch_bounds__(256) void gemm_kernel(
    const float* __restrict__ A, int lda,
    const float* __restrict__ W,        // [N, K] row-major
    float* __restrict__ C, int ldc,
    int N, int K,
    const float* __restrict__ bias)
{
    const int BM = 128, BN = 64, BK = 16;
    __shared__ float As[BK][BM + 4];
    __shared__ float Ws[BK][BN + 4];

    int tid = threadIdx.x;
    int tx = tid & 15;        // n direction (16 * 4 = 64)
    int ty = tid >> 4;        // m direction (16 * 8 = 128)
    int m0 = blockIdx.x * BM;
    int n0 = blockIdx.y * BN;

    float acc[8][4];
#pragma unroll
    for (int i = 0; i < 8; i++)
#pragma unroll
        for (int j = 0; j < 4; j++) acc[i][j] = 0.f;

    int aRow0 = tid >> 2;            // 0..63
    int aC4   = (tid & 3) << 2;      // 0,4,8,12
    int wRow  = tid >> 2;            // 0..63
    int wC4   = (tid & 3) << 2;

    for (int k0 = 0; k0 < K; k0 += BK) {
        // load A tile (128x16) : 2 float4 per thread
#pragma unroll
        for (int r = 0; r < 2; r++) {
            int row = aRow0 + r * 64;
            float4 v = *reinterpret_cast<const float4*>(
                A + (size_t)(m0 + row) * lda + k0 + aC4);
            As[aC4 + 0][row] = v.x; As[aC4 + 1][row] = v.y;
            As[aC4 + 2][row] = v.z; As[aC4 + 3][row] = v.w;
        }
        // load W tile (64x16) : 1 float4 per thread, N-guarded
        {
            float4 v = make_float4(0.f, 0.f, 0.f, 0.f);
            if (n0 + wRow < N)
                v = *reinterpret_cast<const float4*>(
                    W + (size_t)(n0 + wRow) * K + k0 + wC4);
            Ws[wC4 + 0][wRow] = v.x; Ws[wC4 + 1][wRow] = v.y;
            Ws[wC4 + 2][wRow] = v.z; Ws[wC4 + 3][wRow] = v.w;
        }
        __syncthreads();
#pragma unroll
        for (int kk = 0; kk < BK; kk++) {
            float4 a0 = *reinterpret_cast<const float4*>(&As[kk][ty * 8]);
            float4 a1 = *reinterpret_cast<const float4*>(&As[kk][ty * 8 + 4]);
            float4 w0 = *reinterpret_cast<const float4*>(&Ws[kk][tx * 4]);
            float a[8] = {a0.x, a0.y, a0.z, a0.w, a1.x, a1.y, a1.z, a1.w};
            float wv[4] = {w0.x, w0.y, w0.z, w0.w};
#pragma unroll
            for (int i = 0; i < 8; i++)
#pragma unroll
                for (int j = 0; j < 4; j++)
                    acc[i][j] = fmaf(a[i], wv[j], acc[i][j]);
        }
        __syncthreads();
    }

    int nb = n0 + tx * 4;
    if (nb < N) {
        float4 bb = make_float4(0.f, 0.f, 0.f, 0.f);
        if (EPI >= 1) bb = *reinterpret_cast<const float4*>(bias + nb);
#pragma unroll
        for (int i = 0; i < 8; i++) {
            int m = m0 + ty * 8 + i;
            float4 v;
            v.x = acc[i][0]; v.y = acc[i][1]; v.z = acc[i][2]; v.w = acc[i][3];
            if (EPI >= 1) { v.x += bb.x; v.y += bb.y; v.z += bb.z; v.w += bb.w; }
            if (EPI == 2) {
                v.x = softplus_f(v.x); v.y = softplus_f(v.y);
                v.z = softplus_f(v.z); v.w = softplus_f(v.w);
            }
            *reinterpret_cast<float4*>(C + (size_t)m * ldc + nb) = v;
        }
    }
}

// ---------------- A2 precompute: A*log2e = -exp(A_log)*log2(e) ----------------
__global__ void a2_kernel(const float* __restrict__ A_log) {
    int i = blockIdx.x * blockDim.x + threadIdx.x;
    if (i < NLAYERS * DINNER * DSTATE)
        g_A2[i] = -expf(A_log[i]) * 1.4426950408889634f;
}

// ---------------- causal depthwise conv1d (k=4) + bias + silu ----------------
// reads xm = g_xz[:, 0:DINNER] (ld = 2*DINNER), writes g_xc (u)
__global__ __launch_bounds__(256) void conv_kernel(
    const float* __restrict__ cw,   // [DINNER, 4]
    const float* __restrict__ cb)   // [DINNER]
{
    int idx = blockIdx.x * blockDim.x + threadIdx.x;  // over NTOK*DINNER
    int d = idx & (DINNER - 1);
    int t = idx >> 10;              // token index b*L + l
    int l = t & (LSEQ - 1);
    float4 w = *reinterpret_cast<const float4*>(cw + d * 4);
    const float* base = g_xz + (size_t)t * (2 * DINNER) + d;
    float acc = cb[d];
    if (l >= 3) acc = fmaf(w.x, base[-3 * (2 * DINNER)], acc);
    if (l >= 2) acc = fmaf(w.y, base[-2 * (2 * DINNER)], acc);
    if (l >= 1) acc = fmaf(w.z, base[-(2 * DINNER)], acc);
    acc = fmaf(w.w, base[0], acc);
    g_xc[(size_t)t * DINNER + d] = silu_f(acc);
}

// ---------------- selective scan ----------------
// warp = (b, d) channel; lane = state s (DSTATE == 32).
// h_{t} = exp(delta*A[s]) * h_{t-1} + delta*B_t[s]*u_t ; y_t = sum_s h_t * C_t[s]
// y_out = (y + u*D[d]) * silu(res)
__global__ __launch_bounds__(256) void scan_kernel(
    int layer, const float* __restrict__ Dvec)   // Dvec = D + layer*DINNER
{
    int w    = (blockIdx.x * blockDim.x + threadIdx.x) >> 5;
    int lane = threadIdx.x & 31;
    int b = w >> 10;
    int d = w & (DINNER - 1);

    const float* dp = g_delta + (size_t)(b * LSEQ) * DINNER + d;          // stride DINNER
    const float* up = g_xc    + (size_t)(b * LSEQ) * DINNER + d;          // stride DINNER
    const float* rp = g_xz    + (size_t)(b * LSEQ) * (2 * DINNER) + DINNER + d; // stride 2*DINNER
    const float* Bp = g_dbc   + (size_t)(b * LSEQ) * DBCW + DTRANK + lane; // stride DBCW
    float*       yp = g_y     + (size_t)(b * LSEQ) * DINNER + d;

    float a2 = g_A2[layer * DINNER * DSTATE + d * DSTATE + lane];
    float Dd = Dvec[d];
    float hs = 0.f;

#pragma unroll 4
    for (int l = 0; l < LSEQ; l++) {
        float dlt = __ldg(dp);
        float u   = __ldg(up);
        float Bv  = __ldg(Bp);
        float Cv  = __ldg(Bp + DSTATE);
        float dA  = ex2f(dlt * a2);          // exp(delta * A[s]) via one EX2
        hs = fmaf(dA, hs, dlt * u * Bv);
        float py = hs * Cv;
#pragma unroll
        for (int o = 16; o > 0; o >>= 1)
            py += __shfl_xor_sync(0xffffffffu, py, o);
        if (lane == 0) {
            float r = *rp;
            *yp = (py + u * Dd) * silu_f(r);
        }
        dp += DINNER; up += DINNER; Bp += DBCW;
        rp += 2 * DINNER; yp += DINNER;
    }
}

// ---------------- LayerNorm over DMODEL=512, one warp per row ----------------
// reads g_gout, writes g_h
__global__ __launch_bounds__(256) void ln_kernel(
    const float* __restrict__ gam, const float* __restrict__ bet)
{
    int warp = (blockIdx.x * blockDim.x + threadIdx.x) >> 5;
    int lane = threadIdx.x & 31;
    const float* row = g_gout + (size_t)warp * DMODEL;
    float v[16];
#pragma unroll
    for (int i = 0; i < 4; i++) {
        float4 t = *reinterpret_cast<const float4*>(&row[lane * 4 + i * 128]);
        v[i * 4 + 0] = t.x; v[i * 4 + 1] = t.y; v[i * 4 + 2] = t.z; v[i * 4 + 3] = t.w;
    }
    float s = 0.f;
#pragma unroll
    for (int i = 0; i < 16; i++) s += v[i];
#pragma unroll
    for (int o = 16; o > 0; o >>= 1) s += __shfl_xor_sync(0xffffffffu, s, o);
    float mu = s * (1.f / DMODEL);
    float q = 0.f;
#pragma unroll
    for (int i = 0; i < 16; i++) { float e = v[i] - mu; q = fmaf(e, e, q); }
#pragma unroll
    for (int o = 16; o > 0; o >>= 1) q += __shfl_xor_sync(0xffffffffu, q, o);
    float rs = rsqrtf(q * (1.f / DMODEL) + 1e-5f);
    float* orow = g_h + (size_t)warp * DMODEL;
#pragma unroll
    for (int i = 0; i < 4; i++) {
        int c = lane * 4 + i * 128;
        float4 gg = *reinterpret_cast<const float4*>(&gam[c]);
        float4 bb = *reinterpret_cast<const float4*>(&bet[c]);
        float4 o;
        o.x = (v[i*4+0] - mu) * rs * gg.x + bb.x;
        o.y = (v[i*4+1] - mu) * rs * gg.y + bb.y;
        o.z = (v[i*4+2] - mu) * rs * gg.z + bb.z;
        o.w = (v[i*4+3] - mu) * rs * gg.w + bb.w;
        *reinterpret_cast<float4*>(&orow[c]) = o;
    }
}

// ---------------- mean pool over L ----------------
__global__ void pool_kernel() {
    int b = blockIdx.x;       // 8 blocks
    int c = threadIdx.x;      // 512 threads
    float s = 0.f;
    for (int l = 0; l < LSEQ; l++)
        s += g_h[(size_t)(b * LSEQ + l) * DMODEL + c];
    g_pool[b * DMODEL + c] = s * (1.f / LSEQ);
}

// ---------------- classifier head ----------------
__global__ void head_kernel(const float* __restrict__ Wout,
                            const float* __restrict__ bout,
                            float* __restrict__ out)
{
    int idx = blockIdx.x * blockDim.x + threadIdx.x;
    if (idx >= BATCH * NCLASSES) return;
    int m = idx / NCLASSES, n = idx % NCLASSES;
    const float* p = g_pool + m * DMODEL;
    const float* wr = Wout + (size_t)n * DMODEL;
    float s = bout[n];
    for (int k = 0; k < DMODEL; k += 4) {
        float4 a = *reinterpret_cast<const float4*>(p + k);
        float4 w = *reinterpret_cast<const float4*>(wr + k);
        s = fmaf(a.x, w.x, s); s = fmaf(a.y, w.y, s);
        s = fmaf(a.z, w.z, s); s = fmaf(a.w, w.w, s);
    }
    out[idx] = s;
}

// ---------------- launcher ----------------
extern "C" void kernel_launch(void* const* d_in, const int* in_sizes, int n_in,
                              void* d_out, int out_size)
{
    const float* x      = (const float*)d_in[0];
    const float* Wp     = (const float*)d_in[1];
    const float* bp     = (const float*)d_in[2];
    const float* Wi     = (const float*)d_in[3];
    const float* conv_w = (const float*)d_in[4];
    const float* conv_b = (const float*)d_in[5];
    const float* Wx     = (const float*)d_in[6];
    const float* Wdt    = (const float*)d_in[7];
    const float* bdt    = (const float*)d_in[8];
    const float* A_log  = (const float*)d_in[9];
    const float* Dv     = (const float*)d_in[10];
    const float* Wo     = (const float*)d_in[11];
    const float* ln_g   = (const float*)d_in[12];
    const float* ln_b   = (const float*)d_in[13];
    const float* Wout   = (const float*)d_in[14];
    const float* bout   = (const float*)d_in[15];
    float* out = (float*)d_out;

    float *p_h, *p_xz, *p_xc, *p_dbc, *p_delta, *p_y, *p_gout;
    cudaGetSymbolAddress((void**)&p_h,     g_h);
    cudaGetSymbolAddress((void**)&p_xz,    g_xz);
    cudaGetSymbolAddress((void**)&p_xc,    g_xc);
    cudaGetSymbolAddress((void**)&p_dbc,   g_dbc);
    cudaGetSymbolAddress((void**)&p_delta, g_delta);
    cudaGetSymbolAddress((void**)&p_y,     g_y);
    cudaGetSymbolAddress((void**)&p_gout,  g_gout);

    // A2 precompute (recomputed every call: deterministic)
    a2_kernel<<<(NLAYERS * DINNER * DSTATE + 255) / 256, 256>>>(A_log);

    // input projection: h = x @ Wp^T + bp   [8192,128]x[512,128]^T
    gemm_kernel<1><<<dim3(NTOK / 128, DMODEL / 64), 256>>>(
        x, NMELS, Wp, p_h, DMODEL, DMODEL, NMELS, bp);

    for (int lyr = 0; lyr < NLAYERS; lyr++) {
        // in_proj: xz = h @ Wi^T   [8192,512] x [2048,512]^T
        gemm_kernel<0><<<dim3(NTOK / 128, (2 * DINNER) / 64), 256>>>(
            p_h, DMODEL, Wi + (size_t)lyr * 2 * DINNER * DMODEL,
            p_xz, 2 * DINNER, 2 * DINNER, DMODEL, nullptr);

        // causal depthwise conv + silu -> u
        conv_kernel<<<(NTOK * DINNER) / 256, 256>>>(
            conv_w + lyr * DINNER * DCONV, conv_b + lyr * DINNER);

        // x_proj: dbc = u @ Wx^T   [8192,1024] x [96,1024]^T
        gemm_kernel<0><<<dim3(NTOK / 128, (DBCW + 63) / 64), 256>>>(
            p_xc, DINNER, Wx + (size_t)lyr * DBCW * DINNER,
            p_dbc, DBCW, DBCW, DINNER, nullptr);

        // dt_proj + softplus: delta = softplus(dt @ Wdt^T + bdt)
        gemm_kernel<2><<<dim3(NTOK / 128, DINNER / 64), 256>>>(
            p_dbc, DBCW, Wdt + (size_t)lyr * DINNER * DTRANK,
            p_delta, DINNER, DINNER, DTRANK, bdt + lyr * DINNER);

        // selective scan + skip + gate : one warp per (b,d) channel
        // BATCH*DINNER = 8192 warps / 8 warps per block = 1024 blocks
        scan_kernel<<<(BATCH * DINNER) / 8, 256>>>(lyr, Dv + lyr * DINNER);

        // out_proj: gout = y @ Wo^T   [8192,1024] x [512,1024]^T
        gemm_kernel<0><<<dim3(NTOK / 128, DMODEL / 64), 256>>>(
            p_y, DINNER, Wo + (size_t)lyr * DMODEL * DINNER,
            p_gout, DMODEL, DMODEL, DINNER, nullptr);

        // layernorm -> h
        ln_kernel<<<NTOK * 32 / 256, 256>>>(ln_g + lyr * DMODEL, ln_b + lyr * DMODEL);
    }

    pool_kernel<<<BATCH, DMODEL>>>();
    head_kernel<<<(BATCH * NCLASSES + 255) / 256, 256>>>(Wout, bout, out);
}

// round 3
// speedup vs baseline: 1.1121x; 1.1121x over previous
#include <cuda_runtime.h>
#include <math.h>
#include <stdint.h>

// ---------------- problem constants ----------------
#define BATCH    8
#define LSEQ     1024
#define DMODEL   512
#define DINNER   1024     // 2*DMODEL
#define DSTATE   32
#define DCONV    4
#define DTRANK   32
#define NLAYERS  2
#define NMELS    128
#define NCLASSES 1251
#define NTOK     (BATCH*LSEQ)      // 8192
#define DBCW     (DTRANK + 2*DSTATE) // 96

// ---------------- scratch ----------------
__device__ float g_h    [NTOK * DMODEL];
__device__ float g_xz   [NTOK * 2 * DINNER];
__device__ float g_xc   [NTOK * DINNER];
__device__ float g_dbc  [NTOK * DBCW];
__device__ float g_delta[NTOK * DINNER];
__device__ float g_y    [NTOK * DINNER];
__device__ float g_gout [NTOK * DMODEL];
__device__ float g_A2   [NLAYERS * DINNER * DSTATE];
__device__ float g_pool [BATCH * DMODEL];

// ---------------- helpers ----------------
__device__ __forceinline__ float ex2f(float x) {
    float y; asm("ex2.approx.ftz.f32 %0, %1;" : "=f"(y) : "f"(x)); return y;
}
__device__ __forceinline__ float softplus_f(float x) {
    return (x > 20.f) ? x : log1pf(expf(x));
}
__device__ __forceinline__ float silu_f(float x) {
    return x / (1.f + expf(-x));
}
__device__ __forceinline__ uint32_t f2tf32(float x) {
    uint32_t r; asm("cvt.rna.tf32.f32 %0, %1;" : "=r"(r) : "f"(x)); return r;
}
__device__ __forceinline__ void mma_tf32(
    float& d0, float& d1, float& d2, float& d3,
    uint32_t a0, uint32_t a1, uint32_t a2, uint32_t a3,
    uint32_t b0, uint32_t b1)
{
    asm volatile(
        "mma.sync.aligned.m16n8k8.row.col.f32.tf32.tf32.f32 "
        "{%0,%1,%2,%3}, {%4,%5,%6,%7}, {%8,%9}, {%0,%1,%2,%3};\n"
        : "+f"(d0), "+f"(d1), "+f"(d2), "+f"(d3)
        : "r"(a0), "r"(a1), "r"(a2), "r"(a3), "r"(b0), "r"(b1));
}

// ---------------- tf32 tensor-core GEMM ----------------
// C[M,N] = A[M,K] @ W[N,K]^T (+bias)(+softplus)
// BM=128 BN=64 BK=32, 256 threads = 8 warps (4 in M x 2 in N),
// warp tile 32x32 = 2x4 mma tiles of m16n8k8.
// Requirements: M % 128 == 0, K % 32 == 0, lda/ldW rows 16B-aligned.
// N guarded. EPI: 0=none, 1=+bias[n], 2=softplus(acc+bias[n])
template<int EPI>
__global__ __launch_bounds__(256) void mma_gemm(
    const float* __restrict__ A, int lda,
    const float* __restrict__ W,        // [N, K] row-major
    float* __restrict__ C, int ldc,
    int N, int K,
    const float* __restrict__ bias)
{
    const int BM = 128, BN = 64, BK = 32;
    __shared__ uint32_t As[BK][BM + 1];   // [k][m], tf32 bits
    __shared__ uint32_t Ws[BK][BN + 1];   // [k][n], tf32 bits

    const int tid  = threadIdx.x;
    const int wid  = tid >> 5;
    const int lane = tid & 31;
    const int group = lane >> 2;      // 0..7
    const int tg    = lane & 3;       // 0..3
    const int wm = wid & 3;           // warp M index (0..3)
    const int wn = wid >> 2;          // warp N index (0..1)
    const int m0 = blockIdx.x * BM;
    const int n0 = blockIdx.y * BN;

    float acc[2][4][4];
#pragma unroll
    for (int i = 0; i < 2; i++)
#pragma unroll
        for (int j = 0; j < 4; j++)
#pragma unroll
            for (int c = 0; c < 4; c++) acc[i][j][c] = 0.f;

    for (int k0 = 0; k0 < K; k0 += BK) {
        // stage A tile: 128x32 floats = 1024 float4, 4 per thread
#pragma unroll
        for (int t = 0; t < 4; t++) {
            int id = tid + t * 256;
            int m  = id >> 3;               // 0..127
            int kc = (id & 7) << 2;         // 0,4,...,28
            float4 v = *reinterpret_cast<const float4*>(
                A + (size_t)(m0 + m) * lda + k0 + kc);
            As[kc + 0][m] = f2tf32(v.x);
            As[kc + 1][m] = f2tf32(v.y);
            As[kc + 2][m] = f2tf32(v.z);
            As[kc + 3][m] = f2tf32(v.w);
        }
        // stage W tile: 64x32 floats = 512 float4, 2 per thread (N-guarded)
#pragma unroll
        for (int t = 0; t < 2; t++) {
            int id = tid + t * 256;
            int n  = id >> 3;
            int kc = (id & 7) << 2;
            float4 v = make_float4(0.f, 0.f, 0.f, 0.f);
            if (n0 + n < N)
                v = *reinterpret_cast<const float4*>(
                    W + (size_t)(n0 + n) * K + k0 + kc);
            Ws[kc + 0][n] = f2tf32(v.x);
            Ws[kc + 1][n] = f2tf32(v.y);
            Ws[kc + 2][n] = f2tf32(v.z);
            Ws[kc + 3][n] = f2tf32(v.w);
        }
        __syncthreads();

#pragma unroll
        for (int kk = 0; kk < BK; kk += 8) {
            uint32_t af[2][4], bf[4][2];
#pragma unroll
            for (int i = 0; i < 2; i++) {
                int mrow = wm * 32 + i * 16 + group;
                af[i][0] = As[kk + tg    ][mrow    ];
                af[i][1] = As[kk + tg    ][mrow + 8];
                af[i][2] = As[kk + tg + 4][mrow    ];
                af[i][3] = As[kk + tg + 4][mrow + 8];
            }
#pragma unroll
            for (int j = 0; j < 4; j++) {
                int ncol = wn * 32 + j * 8 + group;
                bf[j][0] = Ws[kk + tg    ][ncol];
                bf[j][1] = Ws[kk + tg + 4][ncol];
            }
#pragma unroll
            for (int i = 0; i < 2; i++)
#pragma unroll
                for (int j = 0; j < 4; j++)
                    mma_tf32(acc[i][j][0], acc[i][j][1], acc[i][j][2], acc[i][j][3],
                             af[i][0], af[i][1], af[i][2], af[i][3],
                             bf[j][0], bf[j][1]);
        }
        __syncthreads();
    }

    // epilogue: c0,c1 at (row, col),(row, col+1); c2,c3 at (row+8, col..)
#pragma unroll
    for (int i = 0; i < 2; i++) {
#pragma unroll
        for (int j = 0; j < 4; j++) {
            int row = m0 + wm * 32 + i * 16 + group;
            int col = n0 + wn * 32 + j * 8 + tg * 2;
            if (col < N) {
                float b0 = 0.f, b1 = 0.f;
                if (EPI >= 1) { b0 = bias[col]; b1 = bias[col + 1]; }
                float v0 = acc[i][j][0] + b0, v1 = acc[i][j][1] + b1;
                float v2 = acc[i][j][2] + b0, v3 = acc[i][j][3] + b1;
                if (EPI == 2) {
                    v0 = softplus_f(v0); v1 = softplus_f(v1);
                    v2 = softplus_f(v2); v3 = softplus_f(v3);
                }
                *reinterpret_cast<float2*>(C + (size_t)row * ldc + col)
                    = make_float2(v0, v1);
                *reinterpret_cast<float2*>(C + (size_t)(row + 8) * ldc + col)
                    = make_float2(v2, v3);
            }
        }
    }
}

// ---------------- A2 precompute ----------------
__global__ void a2_kernel(const float* __restrict__ A_log) {
    int i = blockIdx.x * blockDim.x + threadIdx.x;
    if (i < NLAYERS * DINNER * DSTATE)
        g_A2[i] = -expf(A_log[i]) * 1.4426950408889634f;
}

// ---------------- causal depthwise conv1d (k=4) + bias + silu, ILP=4 ----------------
__global__ __launch_bounds__(256) void conv_kernel(
    const float* __restrict__ cw, const float* __restrict__ cb)
{
    int idx = blockIdx.x * blockDim.x + threadIdx.x;   // NTOK*DINNER/4 threads
    int d  = idx & (DINNER - 1);
    int r  = idx >> 10;
    int lg = r & (LSEQ / 4 - 1);
    int b  = r >> 8;
    int l0 = lg * 4;
    int t0 = b * LSEQ + l0;
    const float* base = g_xz + (size_t)t0 * (2 * DINNER) + d;
    float v[7];
#pragma unroll
    for (int i = 0; i < 7; i++) {
        int l = l0 - 3 + i;
        v[i] = (l >= 0) ? base[(i - 3) * (2 * DINNER)] : 0.f;
    }
    float4 w = *reinterpret_cast<const float4*>(cw + d * 4);
    float bias = cb[d];
    float* o = g_xc + (size_t)t0 * DINNER + d;
#pragma unroll
    for (int j = 0; j < 4; j++) {
        float acc = bias;
        acc = fmaf(w.x, v[j],     acc);
        acc = fmaf(w.y, v[j + 1], acc);
        acc = fmaf(w.z, v[j + 2], acc);
        acc = fmaf(w.w, v[j + 3], acc);
        o[j * DINNER] = silu_f(acc);
    }
}

// ---------------- selective scan: warp = (b,d), lane = state ----------------
__global__ __launch_bounds__(256) void scan_kernel(
    int layer, const float* __restrict__ Dvec)
{
    int w    = (blockIdx.x * blockDim.x + threadIdx.x) >> 5;
    int lane = threadIdx.x & 31;
    int b = w >> 10;
    int d = w & (DINNER - 1);

    const float* dp = g_delta + (size_t)(b * LSEQ) * DINNER + d;
    const float* up = g_xc    + (size_t)(b * LSEQ) * DINNER + d;
    const float* rp = g_xz    + (size_t)(b * LSEQ) * (2 * DINNER) + DINNER + d;
    const float* Bp = g_dbc   + (size_t)(b * LSEQ) * DBCW + DTRANK + lane;
    float*       yp = g_y     + (size_t)(b * LSEQ) * DINNER + d;

    float a2 = g_A2[layer * DINNER * DSTATE + d * DSTATE + lane];
    float Dd = Dvec[d];
    float hs = 0.f;

#pragma unroll 4
    for (int l = 0; l < LSEQ; l++) {
        float dlt = __ldg(dp);
        float u   = __ldg(up);
        float Bv  = __ldg(Bp);
        float Cv  = __ldg(Bp + DSTATE);
        float dA  = ex2f(dlt * a2);
        hs = fmaf(dA, hs, dlt * u * Bv);
        float py = hs * Cv;
#pragma unroll
        for (int o = 16; o > 0; o >>= 1)
            py += __shfl_xor_sync(0xffffffffu, py, o);
        if (lane == 0) {
            float r = *rp;
            *yp = (py + u * Dd) * silu_f(r);
        }
        dp += DINNER; up += DINNER; Bp += DBCW;
        rp += 2 * DINNER; yp += DINNER;
    }
}

// ---------------- LayerNorm over DMODEL=512, one warp per row ----------------
__global__ __launch_bounds__(256) void ln_kernel(
    const float* __restrict__ gam, const float* __restrict__ bet)
{
    int warp = (blockIdx.x * blockDim.x + threadIdx.x) >> 5;
    int lane = threadIdx.x & 31;
    const float* row = g_gout + (size_t)warp * DMODEL;
    float v[16];
#pragma unroll
    for (int i = 0; i < 4; i++) {
        float4 t = *reinterpret_cast<const float4*>(&row[lane * 4 + i * 128]);
        v[i * 4 + 0] = t.x; v[i * 4 + 1] = t.y; v[i * 4 + 2] = t.z; v[i * 4 + 3] = t.w;
    }
    float s = 0.f;
#pragma unroll
    for (int i = 0; i < 16; i++) s += v[i];
#pragma unroll
    for (int o = 16; o > 0; o >>= 1) s += __shfl_xor_sync(0xffffffffu, s, o);
    float mu = s * (1.f / DMODEL);
    float q = 0.f;
#pragma unroll
    for (int i = 0; i < 16; i++) { float e = v[i] - mu; q = fmaf(e, e, q); }
#pragma unroll
    for (int o = 16; o > 0; o >>= 1) q += __shfl_xor_sync(0xffffffffu, q, o);
    float rs = rsqrtf(q * (1.f / DMODEL) + 1e-5f);
    float* orow = g_h + (size_t)warp * DMODEL;
#pragma unroll
    for (int i = 0; i < 4; i++) {
        int c = lane * 4 + i * 128;
        float4 gg = *reinterpret_cast<const float4*>(&gam[c]);
        float4 bb = *reinterpret_cast<const float4*>(&bet[c]);
        float4 o;
        o.x = (v[i*4+0] - mu) * rs * gg.x + bb.x;
        o.y = (v[i*4+1] - mu) * rs * gg.y + bb.y;
        o.z = (v[i*4+2] - mu) * rs * gg.z + bb.z;
        o.w = (v[i*4+3] - mu) * rs * gg.w + bb.w;
        *reinterpret_cast<float4*>(&orow[c]) = o;
    }
}

// ---------------- mean pool ----------------
__global__ void pool_kernel() {
    int b = blockIdx.x;
    int c = threadIdx.x;
    float s = 0.f;
    for (int l = 0; l < LSEQ; l++)
        s += g_h[(size_t)(b * LSEQ + l) * DMODEL + c];
    g_pool[b * DMODEL + c] = s * (1.f / LSEQ);
}

// ---------------- classifier head ----------------
__global__ void head_kernel(const float* __restrict__ Wout,
                            const float* __restrict__ bout,
                            float* __restrict__ out)
{
    int idx = blockIdx.x * blockDim.x + threadIdx.x;
    if (idx >= BATCH * NCLASSES) return;
    int m = idx / NCLASSES, n = idx % NCLASSES;
    const float* p = g_pool + m * DMODEL;
    const float* wr = Wout + (size_t)n * DMODEL;
    float s = bout[n];
    for (int k = 0; k < DMODEL; k += 4) {
        float4 a = *reinterpret_cast<const float4*>(p + k);
        float4 w = *reinterpret_cast<const float4*>(wr + k);
        s = fmaf(a.x, w.x, s); s = fmaf(a.y, w.y, s);
        s = fmaf(a.z, w.z, s); s = fmaf(a.w, w.w, s);
    }
    out[idx] = s;
}

// ---------------- launcher ----------------
extern "C" void kernel_launch(void* const* d_in, const int* in_sizes, int n_in,
                              void* d_out, int out_size)
{
    const float* x      = (const float*)d_in[0];
    const float* Wp     = (const float*)d_in[1];
    const float* bp     = (const float*)d_in[2];
    const float* Wi     = (const float*)d_in[3];
    const float* conv_w = (const float*)d_in[4];
    const float* conv_b = (const float*)d_in[5];
    const float* Wx     = (const float*)d_in[6];
    const float* Wdt    = (const float*)d_in[7];
    const float* bdt    = (const float*)d_in[8];
    const float* A_log  = (const float*)d_in[9];
    const float* Dv     = (const float*)d_in[10];
    const float* Wo     = (const float*)d_in[11];
    const float* ln_g   = (const float*)d_in[12];
    const float* ln_b   = (const float*)d_in[13];
    const float* Wout   = (const float*)d_in[14];
    const float* bout   = (const float*)d_in[15];
    float* out = (float*)d_out;

    float *p_h, *p_xz, *p_xc, *p_dbc, *p_delta, *p_y, *p_gout;
    cudaGetSymbolAddress((void**)&p_h,     g_h);
    cudaGetSymbolAddress((void**)&p_xz,    g_xz);
    cudaGetSymbolAddress((void**)&p_xc,    g_xc);
    cudaGetSymbolAddress((void**)&p_dbc,   g_dbc);
    cudaGetSymbolAddress((void**)&p_delta, g_delta);
    cudaGetSymbolAddress((void**)&p_y,     g_y);
    cudaGetSymbolAddress((void**)&p_gout,  g_gout);

    a2_kernel<<<(NLAYERS * DINNER * DSTATE + 255) / 256, 256>>>(A_log);

    // input projection: [8192,128] x [512,128]^T + bias
    mma_gemm<1><<<dim3(NTOK / 128, DMODEL / 64), 256>>>(
        x, NMELS, Wp, p_h, DMODEL, DMODEL, NMELS, bp);

    for (int lyr = 0; lyr < NLAYERS; lyr++) {
        // in_proj: [8192,512] x [2048,512]^T
        mma_gemm<0><<<dim3(NTOK / 128, (2 * DINNER) / 64), 256>>>(
            p_h, DMODEL, Wi + (size_t)lyr * 2 * DINNER * DMODEL,
            p_xz, 2 * DINNER, 2 * DINNER, DMODEL, nullptr);

        // conv + silu -> u (4 outputs/thread)
        conv_kernel<<<(NTOK * DINNER / 4) / 256, 256>>>(
            conv_w + lyr * DINNER * DCONV, conv_b + lyr * DINNER);

        // x_proj: [8192,1024] x [96,1024]^T
        mma_gemm<0><<<dim3(NTOK / 128, 2), 256>>>(
            p_xc, DINNER, Wx + (size_t)lyr * DBCW * DINNER,
            p_dbc, DBCW, DBCW, DINNER, nullptr);

        // dt_proj + softplus: [8192,96(use 32)] x [1024,32]^T
        mma_gemm<2><<<dim3(NTOK / 128, DINNER / 64), 256>>>(
            p_dbc, DBCW, Wdt + (size_t)lyr * DINNER * DTRANK,
            p_delta, DINNER, DINNER, DTRANK, bdt + lyr * DINNER);

        // selective scan: 8192 warps / 8 per block = 1024 blocks
        scan_kernel<<<(BATCH * DINNER) / 8, 256>>>(lyr, Dv + lyr * DINNER);

        // out_proj: [8192,1024] x [512,1024]^T
        mma_gemm<0><<<dim3(NTOK / 128, DMODEL / 64), 256>>>(
            p_y, DINNER, Wo + (size_t)lyr * DMODEL * DINNER,
            p_gout, DMODEL, DMODEL, DINNER, nullptr);

        ln_kernel<<<NTOK * 32 / 256, 256>>>(ln_g + lyr * DMODEL, ln_b + lyr * DMODEL);
    }

    pool_kernel<<<BATCH, DMODEL>>>();
    head_kernel<<<(BATCH * NCLASSES + 255) / 256, 256>>>(Wout, bout, out);
}

// round 5
// speedup vs baseline: 1.4472x; 1.3013x over previous
#include <cuda_runtime.h>
#include <cuda_fp16.h>
#include <math.h>
#include <stdint.h>

// ---------------- problem constants ----------------
#define BATCH    8
#define LSEQ     1024
#define DMODEL   512
#define DINNER   1024
#define DSTATE   32
#define DCONV    4
#define DTRANK   32
#define NLAYERS  2
#define NMELS    128
#define NCLASSES 1251
#define NTOK     (BATCH*LSEQ)
#define DBCW     (DTRANK + 2*DSTATE) // 96

// ---------------- scratch ----------------
__device__ float g_h    [NTOK * DMODEL];
__device__ float g_xz   [NTOK * 2 * DINNER];
__device__ float g_xc   [NTOK * DINNER];
__device__ float g_dbc  [NTOK * DBCW];
__device__ float g_delta[NTOK * DINNER];
__device__ float g_y    [NTOK * DINNER];
__device__ float g_gout [NTOK * DMODEL];
__device__ float g_A2   [NLAYERS * DINNER * DSTATE];
__device__ float g_pool [BATCH * DMODEL];

// ---------------- scalar helpers ----------------
__device__ __forceinline__ float ex2f(float x) {
    float y; asm("ex2.approx.ftz.f32 %0, %1;" : "=f"(y) : "f"(x)); return y;
}
__device__ __forceinline__ float softplus_f(float x) {
    return (x > 20.f) ? x : log1pf(expf(x));
}
__device__ __forceinline__ float silu_f(float x) {
    return x / (1.f + expf(-x));
}
__device__ __forceinline__ uint32_t smem_to_u32(const void* p) {
    uint32_t a;
    asm("{ .reg .u64 t; cvta.to.shared.u64 t, %1; cvt.u32.u64 %0, t; }"
        : "=r"(a) : "l"(p));
    return a;
}

// ---------------- mma / ldmatrix primitives ----------------
__device__ __forceinline__ void ldsm_x4(uint32_t* r, uint32_t addr) {
    asm volatile(
        "ldmatrix.sync.aligned.m8n8.x4.shared.b16 {%0,%1,%2,%3}, [%4];"
        : "=r"(r[0]), "=r"(r[1]), "=r"(r[2]), "=r"(r[3]) : "r"(addr));
}
__device__ __forceinline__ void mma_f16(
    float& c0, float& c1, float& c2, float& c3,
    uint32_t a0, uint32_t a1, uint32_t a2, uint32_t a3,
    uint32_t b0, uint32_t b1)
{
    asm volatile(
        "mma.sync.aligned.m16n8k16.row.col.f32.f16.f16.f32 "
        "{%0,%1,%2,%3}, {%4,%5,%6,%7}, {%8,%9}, {%0,%1,%2,%3};"
        : "+f"(c0), "+f"(c1), "+f"(c2), "+f"(c3)
        : "r"(a0), "r"(a1), "r"(a2), "r"(a3), "r"(b0), "r"(b1));
}

// ---------------- fp16 tensor-core GEMM ----------------
// C[M,N] = A[M,K] @ W[N,K]^T (+bias)(+softplus), fp32 accumulate.
// BM=128, BN=128, BK=64 halves (=128B rows, SW128 chunk-xor layout).
// 256 threads = 8 warps (4 in M x 2 in N), warp tile 32x64.
// M%128==0, K%32==0; N guarded. EPI: 0=none, 1=+bias, 2=softplus(+bias)
#define HGEMM_SMEM (128 + 4*16384)

// stage one 128x64-half tile: G rows [row0, row0+rows), cols [k0, k0+64) of K
__device__ __forceinline__ void stage_tile(
    const float* __restrict__ G, int ldg, int rows_valid, int K, int k0,
    int row0, char* sdst, int tid)
{
#pragma unroll
    for (int i = 0; i < 4; i++) {
        int id  = tid + i * 256;
        int row = id >> 3;
        int ch  = id & 7;
        int k   = k0 + ch * 8;
        uint4 u = make_uint4(0u, 0u, 0u, 0u);
        if (row < rows_valid && k < K) {
            const float* p = G + (size_t)(row0 + row) * ldg + k;
            float4 v0 = *reinterpret_cast<const float4*>(p);
            float4 v1 = *reinterpret_cast<const float4*>(p + 4);
            __half2 h0 = __floats2half2_rn(v0.x, v0.y);
            __half2 h1 = __floats2half2_rn(v0.z, v0.w);
            __half2 h2 = __floats2half2_rn(v1.x, v1.y);
            __half2 h3 = __floats2half2_rn(v1.z, v1.w);
            u.x = *reinterpret_cast<uint32_t*>(&h0);
            u.y = *reinterpret_cast<uint32_t*>(&h1);
            u.z = *reinterpret_cast<uint32_t*>(&h2);
            u.w = *reinterpret_cast<uint32_t*>(&h3);
        }
        *reinterpret_cast<uint4*>(
            sdst + row * 128 + ((ch * 16) ^ ((row & 7) << 4))) = u;
    }
}

template<int EPI>
__global__ __launch_bounds__(256) void hgemm(
    const float* __restrict__ A, int lda,
    const float* __restrict__ W,        // [N, K] row-major
    float* __restrict__ C, int ldc,
    int N, int K,
    const float* __restrict__ bias)
{
    extern __shared__ char sm[];
    uint32_t raw   = smem_to_u32(sm);
    uint32_t base  = (raw + 127u) & ~127u;
    char*    sbase = sm + (base - raw);
    // layout: A0 @0, B0 @16K, A1 @32K, B1 @48K

    const int tid  = threadIdx.x;
    const int wid  = tid >> 5;
    const int lane = tid & 31;
    const int wm = wid & 3;           // 0..3 (M)
    const int wn = wid >> 2;          // 0..1 (N)
    const int g  = lane >> 2;
    const int tg = lane & 3;
    const int m0 = blockIdx.x * 128;
    const int n0 = blockIdx.y * 128;

    float acc[2][8][4];
#pragma unroll
    for (int i = 0; i < 2; i++)
#pragma unroll
        for (int j = 0; j < 8; j++)
#pragma unroll
            for (int c = 0; c < 4; c++) acc[i][j][c] = 0.f;

    const int T = (K + 63) / 64;
    const int nB = N - n0;            // valid B rows in this block

    stage_tile(A, lda, 128, K, 0, m0, sbase,          tid);
    stage_tile(W, K,   nB,  K, 0, n0, sbase + 16384,  tid);
    __syncthreads();

    // per-lane ldmatrix row/k selectors (constant across k16)
    const int a_lrow = lane & 15;           // row within 16-band
    const int a_ksel = (lane >> 4) << 4;    // 0 or 16 bytes (k lo/hi 8 halves)
    const int b_nofs = (((lane >> 4) & 1) << 3) + (lane & 7);
    const int b_ksel = ((lane >> 3) & 1) << 4;

    for (int t = 0; t < T; t++) {
        const int buf = t & 1;
        const uint32_t abase = base + (buf ? 32768u : 0u);
        const uint32_t bbase = abase + 16384u;

        if (t + 1 < T) {
            const int nbuf = 1 - buf;
            stage_tile(A, lda, 128, K, (t + 1) * 64, m0,
                       sbase + (nbuf ? 32768 : 0), tid);
            stage_tile(W, K,   nB,  K, (t + 1) * 64, n0,
                       sbase + (nbuf ? 32768 : 0) + 16384, tid);
        }

#pragma unroll
        for (int k16 = 0; k16 < 4; k16++) {
            const uint32_t kb = k16 * 32;
            uint32_t af[2][4];
#pragma unroll
            for (int i = 0; i < 2; i++) {
                int row = wm * 32 + i * 16 + a_lrow;
                uint32_t addr = abase + row * 128
                              + ((kb + a_ksel) ^ ((row & 7) << 4));
                ldsm_x4(af[i], addr);
            }
            uint32_t bf[4][4];
#pragma unroll
            for (int p = 0; p < 4; p++) {
                int row = wn * 64 + p * 16 + b_nofs;
                uint32_t addr = bbase + row * 128
                              + ((kb + b_ksel) ^ ((row & 7) << 4));
                ldsm_x4(bf[p], addr);
            }
#pragma unroll
            for (int i = 0; i < 2; i++)
#pragma unroll
                for (int p = 0; p < 4; p++) {
                    mma_f16(acc[i][2*p][0], acc[i][2*p][1],
                            acc[i][2*p][2], acc[i][2*p][3],
                            af[i][0], af[i][1], af[i][2], af[i][3],
                            bf[p][0], bf[p][1]);
                    mma_f16(acc[i][2*p+1][0], acc[i][2*p+1][1],
                            acc[i][2*p+1][2], acc[i][2*p+1][3],
                            af[i][0], af[i][1], af[i][2], af[i][3],
                            bf[p][2], bf[p][3]);
                }
        }
        __syncthreads();
    }

    // epilogue
#pragma unroll
    for (int i = 0; i < 2; i++) {
#pragma unroll
        for (int j = 0; j < 8; j++) {
            int row = m0 + wm * 32 + i * 16 + g;
            int col = n0 + wn * 64 + j * 8 + tg * 2;
            if (col < N) {
                float b0 = 0.f, b1 = 0.f;
                if (EPI >= 1) { b0 = bias[col]; b1 = bias[col + 1]; }
                float v0 = acc[i][j][0] + b0, v1 = acc[i][j][1] + b1;
                float v2 = acc[i][j][2] + b0, v3 = acc[i][j][3] + b1;
                if (EPI == 2) {
                    v0 = softplus_f(v0); v1 = softplus_f(v1);
                    v2 = softplus_f(v2); v3 = softplus_f(v3);
                }
                *reinterpret_cast<float2*>(C + (size_t)row * ldc + col)
                    = make_float2(v0, v1);
                *reinterpret_cast<float2*>(C + (size_t)(row + 8) * ldc + col)
                    = make_float2(v2, v3);
            }
        }
    }
}

// ---------------- A2 precompute ----------------
__global__ void a2_kernel(const float* __restrict__ A_log) {
    int i = blockIdx.x * blockDim.x + threadIdx.x;
    if (i < NLAYERS * DINNER * DSTATE)
        g_A2[i] = -expf(A_log[i]) * 1.4426950408889634f;
}

// ---------------- causal depthwise conv1d (k=4) + bias + silu, ILP=4 ----------------
__global__ __launch_bounds__(256) void conv_kernel(
    const float* __restrict__ cw, const float* __restrict__ cb)
{
    int idx = blockIdx.x * blockDim.x + threadIdx.x;
    int d  = idx & (DINNER - 1);
    int r  = idx >> 10;
    int lg = r & (LSEQ / 4 - 1);
    int b  = r >> 8;
    int l0 = lg * 4;
    int t0 = b * LSEQ + l0;
    const float* base = g_xz + (size_t)t0 * (2 * DINNER) + d;
    float v[7];
#pragma unroll
    for (int i = 0; i < 7; i++) {
        int l = l0 - 3 + i;
        v[i] = (l >= 0) ? base[(i - 3) * (2 * DINNER)] : 0.f;
    }
    float4 w = *reinterpret_cast<const float4*>(cw + d * 4);
    float bias = cb[d];
    float* o = g_xc + (size_t)t0 * DINNER + d;
#pragma unroll
    for (int j = 0; j < 4; j++) {
        float acc = bias;
        acc = fmaf(w.x, v[j],     acc);
        acc = fmaf(w.y, v[j + 1], acc);
        acc = fmaf(w.z, v[j + 2], acc);
        acc = fmaf(w.w, v[j + 3], acc);
        o[j * DINNER] = silu_f(acc);
    }
}

// ---------------- selective scan: warp = (b,d), lane = state ----------------
__global__ __launch_bounds__(256) void scan_kernel(
    int layer, const float* __restrict__ Dvec)
{
    int w    = (blockIdx.x * blockDim.x + threadIdx.x) >> 5;
    int lane = threadIdx.x & 31;
    int b = w >> 10;
    int d = w & (DINNER - 1);

    const float* dp = g_delta + (size_t)(b * LSEQ) * DINNER + d;
    const float* up = g_xc    + (size_t)(b * LSEQ) * DINNER + d;
    const float* rp = g_xz    + (size_t)(b * LSEQ) * (2 * DINNER) + DINNER + d;
    const float* Bp = g_dbc   + (size_t)(b * LSEQ) * DBCW + DTRANK + lane;
    float*       yp = g_y     + (size_t)(b * LSEQ) * DINNER + d;

    float a2 = g_A2[layer * DINNER * DSTATE + d * DSTATE + lane];
    float Dd = Dvec[d];
    float hs = 0.f;

#pragma unroll 4
    for (int l = 0; l < LSEQ; l++) {
        float dlt = __ldg(dp);
        float u   = __ldg(up);
        float Bv  = __ldg(Bp);
        float Cv  = __ldg(Bp + DSTATE);
        float dA  = ex2f(dlt * a2);
        hs = fmaf(dA, hs, dlt * u * Bv);
        float py = hs * Cv;
#pragma unroll
        for (int o = 16; o > 0; o >>= 1)
            py += __shfl_xor_sync(0xffffffffu, py, o);
        if (lane == 0) {
            float r = *rp;
            *yp = (py + u * Dd) * silu_f(r);
        }
        dp += DINNER; up += DINNER; Bp += DBCW;
        rp += 2 * DINNER; yp += DINNER;
    }
}

// ---------------- LayerNorm over DMODEL=512, one warp per row ----------------
__global__ __launch_bounds__(256) void ln_kernel(
    const float* __restrict__ gam, const float* __restrict__ bet)
{
    int warp = (blockIdx.x * blockDim.x + threadIdx.x) >> 5;
    int lane = threadIdx.x & 31;
    const float* row = g_gout + (size_t)warp * DMODEL;
    float v[16];
#pragma unroll
    for (int i = 0; i < 4; i++) {
        float4 t = *reinterpret_cast<const float4*>(&row[lane * 4 + i * 128]);
        v[i * 4 + 0] = t.x; v[i * 4 + 1] = t.y; v[i * 4 + 2] = t.z; v[i * 4 + 3] = t.w;
    }
    float s = 0.f;
#pragma unroll
    for (int i = 0; i < 16; i++) s += v[i];
#pragma unroll
    for (int o = 16; o > 0; o >>= 1) s += __shfl_xor_sync(0xffffffffu, s, o);
    float mu = s * (1.f / DMODEL);
    float q = 0.f;
#pragma unroll
    for (int i = 0; i < 16; i++) { float e = v[i] - mu; q = fmaf(e, e, q); }
#pragma unroll
    for (int o = 16; o > 0; o >>= 1) q += __shfl_xor_sync(0xffffffffu, q, o);
    float rs = rsqrtf(q * (1.f / DMODEL) + 1e-5f);
    float* orow = g_h + (size_t)warp * DMODEL;
#pragma unroll
    for (int i = 0; i < 4; i++) {
        int c = lane * 4 + i * 128;
        float4 gg = *reinterpret_cast<const float4*>(&gam[c]);
        float4 bb = *reinterpret_cast<const float4*>(&bet[c]);
        float4 o;
        o.x = (v[i*4+0] - mu) * rs * gg.x + bb.x;
        o.y = (v[i*4+1] - mu) * rs * gg.y + bb.y;
        o.z = (v[i*4+2] - mu) * rs * gg.z + bb.z;
        o.w = (v[i*4+3] - mu) * rs * gg.w + bb.w;
        *reinterpret_cast<float4*>(&orow[c]) = o;
    }
}

// ---------------- mean pool ----------------
__global__ void pool_kernel() {
    int b = blockIdx.x;
    int c = threadIdx.x;
    float s = 0.f;
    for (int l = 0; l < LSEQ; l++)
        s += g_h[(size_t)(b * LSEQ + l) * DMODEL + c];
    g_pool[b * DMODEL + c] = s * (1.f / LSEQ);
}

// ---------------- classifier head ----------------
__global__ void head_kernel(const float* __restrict__ Wout,
                            const float* __restrict__ bout,
                            float* __restrict__ out)
{
    int idx = blockIdx.x * blockDim.x + threadIdx.x;
    if (idx >= BATCH * NCLASSES) return;
    int m = idx / NCLASSES, n = idx % NCLASSES;
    const float* p = g_pool + m * DMODEL;
    const float* wr = Wout + (size_t)n * DMODEL;
    float s = bout[n];
    for (int k = 0; k < DMODEL; k += 4) {
        float4 a = *reinterpret_cast<const float4*>(p + k);
        float4 w = *reinterpret_cast<const float4*>(wr + k);
        s = fmaf(a.x, w.x, s); s = fmaf(a.y, w.y, s);
        s = fmaf(a.z, w.z, s); s = fmaf(a.w, w.w, s);
    }
    out[idx] = s;
}

// ---------------- launcher ----------------
extern "C" void kernel_launch(void* const* d_in, const int* in_sizes, int n_in,
                              void* d_out, int out_size)
{
    const float* x      = (const float*)d_in[0];
    const float* Wp     = (const float*)d_in[1];
    const float* bp     = (const float*)d_in[2];
    const float* Wi     = (const float*)d_in[3];
    const float* conv_w = (const float*)d_in[4];
    const float* conv_b = (const float*)d_in[5];
    const float* Wx     = (const float*)d_in[6];
    const float* Wdt    = (const float*)d_in[7];
    const float* bdt    = (const float*)d_in[8];
    const float* A_log  = (const float*)d_in[9];
    const float* Dv     = (const float*)d_in[10];
    const float* Wo     = (const float*)d_in[11];
    const float* ln_g   = (const float*)d_in[12];
    const float* ln_b   = (const float*)d_in[13];
    const float* Wout   = (const float*)d_in[14];
    const float* bout   = (const float*)d_in[15];
    float* out = (float*)d_out;

    float *p_h, *p_xz, *p_xc, *p_dbc, *p_delta, *p_y, *p_gout;
    cudaGetSymbolAddress((void**)&p_h,     g_h);
    cudaGetSymbolAddress((void**)&p_xz,    g_xz);
    cudaGetSymbolAddress((void**)&p_xc,    g_xc);
    cudaGetSymbolAddress((void**)&p_dbc,   g_dbc);
    cudaGetSymbolAddress((void**)&p_delta, g_delta);
    cudaGetSymbolAddress((void**)&p_y,     g_y);
    cudaGetSymbolAddress((void**)&p_gout,  g_gout);

    cudaFuncSetAttribute(hgemm<0>, cudaFuncAttributeMaxDynamicSharedMemorySize, HGEMM_SMEM);
    cudaFuncSetAttribute(hgemm<1>, cudaFuncAttributeMaxDynamicSharedMemorySize, HGEMM_SMEM);
    cudaFuncSetAttribute(hgemm<2>, cudaFuncAttributeMaxDynamicSharedMemorySize, HGEMM_SMEM);

    a2_kernel<<<(NLAYERS * DINNER * DSTATE + 255) / 256, 256>>>(A_log);

    // input projection: [8192,128] x [512,128]^T + bias
    hgemm<1><<<dim3(NTOK / 128, DMODEL / 128), 256, HGEMM_SMEM>>>(
        x, NMELS, Wp, p_h, DMODEL, DMODEL, NMELS, bp);

    for (int lyr = 0; lyr < NLAYERS; lyr++) {
        // in_proj: [8192,512] x [2048,512]^T
        hgemm<0><<<dim3(NTOK / 128, (2 * DINNER) / 128), 256, HGEMM_SMEM>>>(
            p_h, DMODEL, Wi + (size_t)lyr * 2 * DINNER * DMODEL,
            p_xz, 2 * DINNER, 2 * DINNER, DMODEL, nullptr);

        // conv + silu -> u
        conv_kernel<<<(NTOK * DINNER / 4) / 256, 256>>>(
            conv_w + lyr * DINNER * DCONV, conv_b + lyr * DINNER);

        // x_proj: [8192,1024] x [96,1024]^T (N=96, guarded)
        hgemm<0><<<dim3(NTOK / 128, 1), 256, HGEMM_SMEM>>>(
            p_xc, DINNER, Wx + (size_t)lyr * DBCW * DINNER,
            p_dbc, DBCW, DBCW, DINNER, nullptr);

        // dt_proj + softplus: [8192,32(of 96)] x [1024,32]^T
        hgemm<2><<<dim3(NTOK / 128, DINNER / 128), 256, HGEMM_SMEM>>>(
            p_dbc, DBCW, Wdt + (size_t)lyr * DINNER * DTRANK,
            p_delta, DINNER, DINNER, DTRANK, bdt + lyr * DINNER);

        // selective scan: 8192 warps / 8 per block
        scan_kernel<<<(BATCH * DINNER) / 8, 256>>>(lyr, Dv + lyr * DINNER);

        // out_proj: [8192,1024] x [512,1024]^T
        hgemm<0><<<dim3(NTOK / 128, DMODEL / 128), 256, HGEMM_SMEM>>>(
            p_y, DINNER, Wo + (size_t)lyr * DMODEL * DINNER,
            p_gout, DMODEL, DMODEL, DINNER, nullptr);

        ln_kernel<<<NTOK * 32 / 256, 256>>>(ln_g + lyr * DMODEL, ln_b + lyr * DMODEL);
    }

    pool_kernel<<<BATCH, DMODEL>>>();
    head_kernel<<<(BATCH * NCLASSES + 255) / 256, 256>>>(Wout, bout, out);
}

// round 6
// speedup vs baseline: 1.5124x; 1.0450x over previous
#include <cuda_runtime.h>
#include <cuda_fp16.h>
#include <math.h>
#include <stdint.h>

// ---------------- problem constants ----------------
#define BATCH    8
#define LSEQ     1024
#define DMODEL   512
#define DINNER   1024
#define DSTATE   32
#define DCONV    4
#define DTRANK   32
#define NLAYERS  2
#define NMELS    128
#define NCLASSES 1251
#define NTOK     (BATCH*LSEQ)
#define DBCW     (DTRANK + 2*DSTATE) // 96

// fp16 weight arena offsets (in halves)
#define WP_OFF  0
#define WP_SZ   (DMODEL*NMELS)                 // 65536
#define WI_OFF  (WP_OFF + WP_SZ)
#define WI_SZ   (NLAYERS*2*DINNER*DMODEL)      // 2097152
#define WX_OFF  (WI_OFF + WI_SZ)
#define WX_SZ   (NLAYERS*DBCW*DINNER)          // 196608
#define WDT_OFF (WX_OFF + WX_SZ)
#define WDT_SZ  (NLAYERS*DINNER*DTRANK)        // 65536
#define WO_OFF  (WDT_OFF + WDT_SZ)
#define WO_SZ   (NLAYERS*DMODEL*DINNER)        // 1048576
#define W16_TOTAL (WO_OFF + WO_SZ)
#define X16_SZ  (NTOK*NMELS)

// ---------------- scratch ----------------
__device__ float  g_h    [NTOK * DMODEL];
__device__ float  g_xz   [NTOK * 2 * DINNER];
__device__ float  g_xc   [NTOK * DINNER];
__device__ float  g_dbc  [NTOK * DBCW];
__device__ float  g_delta[NTOK * DINNER];
__device__ float  g_gout [NTOK * DMODEL];
__device__ float  g_A2   [NLAYERS * DINNER * DSTATE];
__device__ float  g_pool [BATCH * DMODEL];
__device__ __half g_w16  [W16_TOTAL];
__device__ __half g_x16  [X16_SZ];
__device__ __half g_h16  [NTOK * DMODEL];
__device__ __half g_xc16 [NTOK * DINNER];
__device__ __half g_dbc16[NTOK * DBCW];
__device__ __half g_y16  [NTOK * DINNER];

// ---------------- scalar helpers ----------------
__device__ __forceinline__ float ex2f(float x) {
    float y; asm("ex2.approx.ftz.f32 %0, %1;" : "=f"(y) : "f"(x)); return y;
}
__device__ __forceinline__ float softplus_f(float x) {
    return (x > 20.f) ? x : log1pf(expf(x));
}
__device__ __forceinline__ float silu_f(float x) {
    return x / (1.f + expf(-x));
}
__device__ __forceinline__ uint32_t smem_to_u32(const void* p) {
    uint32_t a;
    asm("{ .reg .u64 t; cvta.to.shared.u64 t, %1; cvt.u32.u64 %0, t; }"
        : "=r"(a) : "l"(p));
    return a;
}

// ---------------- mma / ldmatrix / cp.async primitives ----------------
__device__ __forceinline__ void ldsm_x4(uint32_t* r, uint32_t addr) {
    asm volatile(
        "ldmatrix.sync.aligned.m8n8.x4.shared.b16 {%0,%1,%2,%3}, [%4];"
        : "=r"(r[0]), "=r"(r[1]), "=r"(r[2]), "=r"(r[3]) : "r"(addr));
}
__device__ __forceinline__ void mma_f16(
    float& c0, float& c1, float& c2, float& c3,
    uint32_t a0, uint32_t a1, uint32_t a2, uint32_t a3,
    uint32_t b0, uint32_t b1)
{
    asm volatile(
        "mma.sync.aligned.m16n8k16.row.col.f32.f16.f16.f32 "
        "{%0,%1,%2,%3}, {%4,%5,%6,%7}, {%8,%9}, {%0,%1,%2,%3};"
        : "+f"(c0), "+f"(c1), "+f"(c2), "+f"(c3)
        : "r"(a0), "r"(a1), "r"(a2), "r"(a3), "r"(b0), "r"(b1));
}
__device__ __forceinline__ void cpa16(uint32_t dst, const void* src, uint32_t sz) {
    asm volatile("cp.async.cg.shared.global [%0], [%1], 16, %2;"
                 :: "r"(dst), "l"(src), "r"(sz) : "memory");
}
__device__ __forceinline__ void cpa_commit() {
    asm volatile("cp.async.commit_group;" ::: "memory");
}
__device__ __forceinline__ void cpa_wait(int rem) {
    if (rem == 0)      asm volatile("cp.async.wait_group 0;" ::: "memory");
    else if (rem == 1) asm volatile("cp.async.wait_group 1;" ::: "memory");
    else               asm volatile("cp.async.wait_group 2;" ::: "memory");
}

// ---------------- fp16 tensor-core GEMM, cp.async 3-stage ----------------
// C = A[M,K](fp16) @ W[N,K](fp16)^T (+bias)(+softplus); fp32 accumulate.
// BM=128, BN=128, BK=64. 256 threads = 8 warps (4M x 2N), warp tile 32x64.
// M%128==0; N,K guarded. WF: write fp32 C, WH: write fp16 C (same ldc).
#define HGEMM_SMEM (128 + 3*32768)

// issue one 128x64-half tile copy (G pre-offset to tile row 0)
__device__ __forceinline__ void stage_async(
    const __half* __restrict__ G, int ldg, int rows_valid, int K, int k0,
    uint32_t sbuf, int tid)
{
#pragma unroll
    for (int i = 0; i < 4; i++) {
        int id  = tid + i * 256;
        int row = id >> 3;
        int ch  = id & 7;
        int k   = k0 + ch * 8;
        uint32_t sz = (row < rows_valid && k < K) ? 16u : 0u;
        const void* src = G + (size_t)row * ldg + k;
        uint32_t dst = sbuf + row * 128 + ((ch * 16) ^ ((row & 7) << 4));
        cpa16(dst, src, sz);
    }
}

template<int EPI, bool WF, bool WH>
__global__ __launch_bounds__(256) void hgemm(
    const __half* __restrict__ A, int lda,
    const __half* __restrict__ W,       // [N, K] row-major fp16
    float* __restrict__ Cf, __half* __restrict__ Ch, int ldc,
    int N, int K,
    const float* __restrict__ bias)
{
    extern __shared__ char sm[];
    uint32_t raw  = smem_to_u32(sm);
    uint32_t base = (raw + 127u) & ~127u;

    const int tid  = threadIdx.x;
    const int wid  = tid >> 5;
    const int lane = tid & 31;
    const int wm = wid & 3;
    const int wn = wid >> 2;
    const int g  = lane >> 2;
    const int tg = lane & 3;
    const int m0 = blockIdx.x * 128;
    const int n0 = blockIdx.y * 128;

    const __half* Ab = A + (size_t)m0 * lda;
    const __half* Wb = W + (size_t)n0 * K;
    int nB = N - n0; if (nB > 128) nB = 128;

    float acc[2][8][4];
#pragma unroll
    for (int i = 0; i < 2; i++)
#pragma unroll
        for (int j = 0; j < 8; j++)
#pragma unroll
            for (int c = 0; c < 4; c++) acc[i][j][c] = 0.f;

    const int T = (K + 63) / 64;

    // prologue: fill up to 3 stages
#pragma unroll
    for (int s = 0; s < 3; s++) {
        if (s < T) {
            stage_async(Ab, lda, 128, K, s * 64, base + s * 32768,           tid);
            stage_async(Wb, K,   nB,  K, s * 64, base + s * 32768 + 16384u,  tid);
            cpa_commit();
        }
    }

    // ldmatrix lane selectors
    const int a_lrow = lane & 15;
    const int a_ksel = (lane >> 4) << 4;
    const int b_nofs = (((lane >> 4) & 1) << 3) + (lane & 7);
    const int b_ksel = ((lane >> 3) & 1) << 4;

    for (int t = 0; t < T; t++) {
        int rem = T - 1 - t; if (rem > 2) rem = 2;
        cpa_wait(rem);
        __syncthreads();

        const int buf = t % 3;
        const uint32_t abase = base + buf * 32768u;
        const uint32_t bbase = abase + 16384u;

#pragma unroll
        for (int k16 = 0; k16 < 4; k16++) {
            const uint32_t kb = k16 * 32;
            uint32_t af[2][4];
#pragma unroll
            for (int i = 0; i < 2; i++) {
                int row = wm * 32 + i * 16 + a_lrow;
                ldsm_x4(af[i], abase + row * 128
                               + ((kb + a_ksel) ^ ((row & 7) << 4)));
            }
            uint32_t bf[4][4];
#pragma unroll
            for (int p = 0; p < 4; p++) {
                int row = wn * 64 + p * 16 + b_nofs;
                ldsm_x4(bf[p], bbase + row * 128
                               + ((kb + b_ksel) ^ ((row & 7) << 4)));
            }
#pragma unroll
            for (int i = 0; i < 2; i++)
#pragma unroll
                for (int p = 0; p < 4; p++) {
                    mma_f16(acc[i][2*p][0], acc[i][2*p][1],
                            acc[i][2*p][2], acc[i][2*p][3],
                            af[i][0], af[i][1], af[i][2], af[i][3],
                            bf[p][0], bf[p][1]);
                    mma_f16(acc[i][2*p+1][0], acc[i][2*p+1][1],
                            acc[i][2*p+1][2], acc[i][2*p+1][3],
                            af[i][0], af[i][1], af[i][2], af[i][3],
                            bf[p][2], bf[p][3]);
                }
        }
        __syncthreads();
        if (t + 3 < T) {
            stage_async(Ab, lda, 128, K, (t + 3) * 64, base + buf * 32768u,          tid);
            stage_async(Wb, K,   nB,  K, (t + 3) * 64, base + buf * 32768u + 16384u, tid);
            cpa_commit();
        }
    }

    // epilogue
#pragma unroll
    for (int i = 0; i < 2; i++) {
#pragma unroll
        for (int j = 0; j < 8; j++) {
            int row = m0 + wm * 32 + i * 16 + g;
            int col = n0 + wn * 64 + j * 8 + tg * 2;
            if (col < N) {
                float b0 = 0.f, b1 = 0.f;
                if (EPI >= 1) { b0 = bias[col]; b1 = bias[col + 1]; }
                float v0 = acc[i][j][0] + b0, v1 = acc[i][j][1] + b1;
                float v2 = acc[i][j][2] + b0, v3 = acc[i][j][3] + b1;
                if (EPI == 2) {
                    v0 = softplus_f(v0); v1 = softplus_f(v1);
                    v2 = softplus_f(v2); v3 = softplus_f(v3);
                }
                if (WF) {
                    *reinterpret_cast<float2*>(Cf + (size_t)row * ldc + col)
                        = make_float2(v0, v1);
                    *reinterpret_cast<float2*>(Cf + (size_t)(row + 8) * ldc + col)
                        = make_float2(v2, v3);
                }
                if (WH) {
                    *reinterpret_cast<__half2*>(Ch + (size_t)row * ldc + col)
                        = __floats2half2_rn(v0, v1);
                    *reinterpret_cast<__half2*>(Ch + (size_t)(row + 8) * ldc + col)
                        = __floats2half2_rn(v2, v3);
                }
            }
        }
    }
}

// ---------------- fp16 conversion of all weights + x (one launch) ----------------
__global__ void wcvt_kernel(
    const float* __restrict__ Wp, const float* __restrict__ Wi,
    const float* __restrict__ Wx, const float* __restrict__ Wdt,
    const float* __restrict__ Wo, const float* __restrict__ x)
{
    int i = blockIdx.x * blockDim.x + threadIdx.x;
    const int C0 = WP_SZ, C1 = C0 + WI_SZ, C2 = C1 + WX_SZ,
              C3 = C2 + WDT_SZ, C4 = C3 + WO_SZ, C5 = C4 + X16_SZ;
    if (i >= C5) return;
    float v; __half* dst;
    if (i < C0)      { v = Wp[i];        dst = g_w16 + WP_OFF  + i; }
    else if (i < C1) { v = Wi[i - C0];   dst = g_w16 + WI_OFF  + (i - C0); }
    else if (i < C2) { v = Wx[i - C1];   dst = g_w16 + WX_OFF  + (i - C1); }
    else if (i < C3) { v = Wdt[i - C2];  dst = g_w16 + WDT_OFF + (i - C2); }
    else if (i < C4) { v = Wo[i - C3];   dst = g_w16 + WO_OFF  + (i - C3); }
    else             { v = x[i - C4];    dst = g_x16 + (i - C4); }
    *dst = __float2half_rn(v);
}

// ---------------- A2 precompute ----------------
__global__ void a2_kernel(const float* __restrict__ A_log) {
    int i = blockIdx.x * blockDim.x + threadIdx.x;
    if (i < NLAYERS * DINNER * DSTATE)
        g_A2[i] = -expf(A_log[i]) * 1.4426950408889634f;
}

// ---------------- causal depthwise conv1d + bias + silu (fp32 + fp16 out) ----
__global__ __launch_bounds__(256) void conv_kernel(
    const float* __restrict__ cw, const float* __restrict__ cb)
{
    int idx = blockIdx.x * blockDim.x + threadIdx.x;
    int d  = idx & (DINNER - 1);
    int r  = idx >> 10;
    int lg = r & (LSEQ / 4 - 1);
    int b  = r >> 8;
    int l0 = lg * 4;
    int t0 = b * LSEQ + l0;
    const float* base = g_xz + (size_t)t0 * (2 * DINNER) + d;
    float v[7];
#pragma unroll
    for (int i = 0; i < 7; i++) {
        int l = l0 - 3 + i;
        v[i] = (l >= 0) ? base[(i - 3) * (2 * DINNER)] : 0.f;
    }
    float4 w = *reinterpret_cast<const float4*>(cw + d * 4);
    float bias = cb[d];
    float*  o   = g_xc   + (size_t)t0 * DINNER + d;
    __half* o16 = g_xc16 + (size_t)t0 * DINNER + d;
#pragma unroll
    for (int j = 0; j < 4; j++) {
        float acc = bias;
        acc = fmaf(w.x, v[j],     acc);
        acc = fmaf(w.y, v[j + 1], acc);
        acc = fmaf(w.z, v[j + 2], acc);
        acc = fmaf(w.w, v[j + 3], acc);
        float s = silu_f(acc);
        o[j * DINNER]   = s;
        o16[j * DINNER] = __float2half_rn(s);
    }
}

// ---------------- selective scan: warp = (b,d), lane = state ----------------
__global__ __launch_bounds__(256) void scan_kernel(
    int layer, const float* __restrict__ Dvec)
{
    int w    = (blockIdx.x * blockDim.x + threadIdx.x) >> 5;
    int lane = threadIdx.x & 31;
    int b = w >> 10;
    int d = w & (DINNER - 1);

    const float* dp = g_delta + (size_t)(b * LSEQ) * DINNER + d;
    const float* up = g_xc    + (size_t)(b * LSEQ) * DINNER + d;
    const float* rp = g_xz    + (size_t)(b * LSEQ) * (2 * DINNER) + DINNER + d;
    const float* Bp = g_dbc   + (size_t)(b * LSEQ) * DBCW + DTRANK + lane;
    __half*      yp = g_y16   + (size_t)(b * LSEQ) * DINNER + d;

    float a2 = g_A2[layer * DINNER * DSTATE + d * DSTATE + lane];
    float Dd = Dvec[d];
    float hs = 0.f;

#pragma unroll 4
    for (int l = 0; l < LSEQ; l++) {
        float dlt = __ldg(dp);
        float u   = __ldg(up);
        float Bv  = __ldg(Bp);
        float Cv  = __ldg(Bp + DSTATE);
        float dA  = ex2f(dlt * a2);
        hs = fmaf(dA, hs, dlt * u * Bv);
        float py = hs * Cv;
#pragma unroll
        for (int o = 16; o > 0; o >>= 1)
            py += __shfl_xor_sync(0xffffffffu, py, o);
        if (lane == 0) {
            float r = *rp;
            *yp = __float2half_rn((py + u * Dd) * silu_f(r));
        }
        dp += DINNER; up += DINNER; Bp += DBCW;
        rp += 2 * DINNER; yp += DINNER;
    }
}

// ---------------- LayerNorm (fp32 + fp16 out) ----------------
__global__ __launch_bounds__(256) void ln_kernel(
    const float* __restrict__ gam, const float* __restrict__ bet)
{
    int warp = (blockIdx.x * blockDim.x + threadIdx.x) >> 5;
    int lane = threadIdx.x & 31;
    const float* row = g_gout + (size_t)warp * DMODEL;
    float v[16];
#pragma unroll
    for (int i = 0; i < 4; i++) {
        float4 t = *reinterpret_cast<const float4*>(&row[lane * 4 + i * 128]);
        v[i * 4 + 0] = t.x; v[i * 4 + 1] = t.y; v[i * 4 + 2] = t.z; v[i * 4 + 3] = t.w;
    }
    float s = 0.f;
#pragma unroll
    for (int i = 0; i < 16; i++) s += v[i];
#pragma unroll
    for (int o = 16; o > 0; o >>= 1) s += __shfl_xor_sync(0xffffffffu, s, o);
    float mu = s * (1.f / DMODEL);
    float q = 0.f;
#pragma unroll
    for (int i = 0; i < 16; i++) { float e = v[i] - mu; q = fmaf(e, e, q); }
#pragma unroll
    for (int o = 16; o > 0; o >>= 1) q += __shfl_xor_sync(0xffffffffu, q, o);
    float rs = rsqrtf(q * (1.f / DMODEL) + 1e-5f);
    float*  orow  = g_h   + (size_t)warp * DMODEL;
    __half* orow16= g_h16 + (size_t)warp * DMODEL;
#pragma unroll
    for (int i = 0; i < 4; i++) {
        int c = lane * 4 + i * 128;
        float4 gg = *reinterpret_cast<const float4*>(&gam[c]);
        float4 bb = *reinterpret_cast<const float4*>(&bet[c]);
        float4 o;
        o.x = (v[i*4+0] - mu) * rs * gg.x + bb.x;
        o.y = (v[i*4+1] - mu) * rs * gg.y + bb.y;
        o.z = (v[i*4+2] - mu) * rs * gg.z + bb.z;
        o.w = (v[i*4+3] - mu) * rs * gg.w + bb.w;
        *reinterpret_cast<float4*>(&orow[c]) = o;
        *reinterpret_cast<__half2*>(&orow16[c])     = __floats2half2_rn(o.x, o.y);
        *reinterpret_cast<__half2*>(&orow16[c + 2]) = __floats2half2_rn(o.z, o.w);
    }
}

// ---------------- mean pool ----------------
__global__ void pool_kernel() {
    int b = blockIdx.x;
    int c = threadIdx.x;
    float s = 0.f;
    for (int l = 0; l < LSEQ; l++)
        s += g_h[(size_t)(b * LSEQ + l) * DMODEL + c];
    g_pool[b * DMODEL + c] = s * (1.f / LSEQ);
}

// ---------------- classifier head ----------------
__global__ void head_kernel(const float* __restrict__ Wout,
                            const float* __restrict__ bout,
                            float* __restrict__ out)
{
    int idx = blockIdx.x * blockDim.x + threadIdx.x;
    if (idx >= BATCH * NCLASSES) return;
    int m = idx / NCLASSES, n = idx % NCLASSES;
    const float* p = g_pool + m * DMODEL;
    const float* wr = Wout + (size_t)n * DMODEL;
    float s = bout[n];
    for (int k = 0; k < DMODEL; k += 4) {
        float4 a = *reinterpret_cast<const float4*>(p + k);
        float4 w = *reinterpret_cast<const float4*>(wr + k);
        s = fmaf(a.x, w.x, s); s = fmaf(a.y, w.y, s);
        s = fmaf(a.z, w.z, s); s = fmaf(a.w, w.w, s);
    }
    out[idx] = s;
}

// ---------------- launcher ----------------
extern "C" void kernel_launch(void* const* d_in, const int* in_sizes, int n_in,
                              void* d_out, int out_size)
{
    const float* x      = (const float*)d_in[0];
    const float* Wp     = (const float*)d_in[1];
    const float* bp     = (const float*)d_in[2];
    const float* Wi     = (const float*)d_in[3];
    const float* conv_w = (const float*)d_in[4];
    const float* conv_b = (const float*)d_in[5];
    const float* Wx     = (const float*)d_in[6];
    const float* Wdt    = (const float*)d_in[7];
    const float* bdt    = (const float*)d_in[8];
    const float* A_log  = (const float*)d_in[9];
    const float* Dv     = (const float*)d_in[10];
    const float* Wo     = (const float*)d_in[11];
    const float* ln_g   = (const float*)d_in[12];
    const float* ln_b   = (const float*)d_in[13];
    const float* Wout   = (const float*)d_in[14];
    const float* bout   = (const float*)d_in[15];
    float* out = (float*)d_out;

    float *p_xz, *p_dbc, *p_delta, *p_gout;
    __half *p_w16, *p_x16, *p_h16, *p_xc16, *p_dbc16, *p_y16;
    cudaGetSymbolAddress((void**)&p_xz,    g_xz);
    cudaGetSymbolAddress((void**)&p_dbc,   g_dbc);
    cudaGetSymbolAddress((void**)&p_delta, g_delta);
    cudaGetSymbolAddress((void**)&p_gout,  g_gout);
    cudaGetSymbolAddress((void**)&p_w16,   g_w16);
    cudaGetSymbolAddress((void**)&p_x16,   g_x16);
    cudaGetSymbolAddress((void**)&p_h16,   g_h16);
    cudaGetSymbolAddress((void**)&p_xc16,  g_xc16);
    cudaGetSymbolAddress((void**)&p_dbc16, g_dbc16);
    cudaGetSymbolAddress((void**)&p_y16,   g_y16);

    cudaFuncSetAttribute(hgemm<1,false,true>, cudaFuncAttributeMaxDynamicSharedMemorySize, HGEMM_SMEM);
    cudaFuncSetAttribute(hgemm<0,true,false>, cudaFuncAttributeMaxDynamicSharedMemorySize, HGEMM_SMEM);
    cudaFuncSetAttribute(hgemm<0,true,true>,  cudaFuncAttributeMaxDynamicSharedMemorySize, HGEMM_SMEM);
    cudaFuncSetAttribute(hgemm<2,true,false>, cudaFuncAttributeMaxDynamicSharedMemorySize, HGEMM_SMEM);

    // 1: convert all weights + x to fp16
    {
        int total = WP_SZ + WI_SZ + WX_SZ + WDT_SZ + WO_SZ + X16_SZ;
        wcvt_kernel<<<(total + 255) / 256, 256>>>(Wp, Wi, Wx, Wdt, Wo, x);
    }
    // 2: A2 precompute
    a2_kernel<<<(NLAYERS * DINNER * DSTATE + 255) / 256, 256>>>(A_log);

    // 3: input projection -> h16 only
    hgemm<1,false,true><<<dim3(NTOK / 128, DMODEL / 128), 256, HGEMM_SMEM>>>(
        p_x16, NMELS, p_w16 + WP_OFF, nullptr, p_h16, DMODEL, DMODEL, NMELS, bp);

    for (int lyr = 0; lyr < NLAYERS; lyr++) {
        // 4 (lyr0, profiled): in_proj -> xz fp32
        hgemm<0,true,false><<<dim3(NTOK / 128, (2 * DINNER) / 128), 256, HGEMM_SMEM>>>(
            p_h16, DMODEL, p_w16 + WI_OFF + (size_t)lyr * 2 * DINNER * DMODEL,
            p_xz, nullptr, 2 * DINNER, 2 * DINNER, DMODEL, nullptr);

        // conv + silu -> xc fp32 + xc16
        conv_kernel<<<(NTOK * DINNER / 4) / 256, 256>>>(
            conv_w + lyr * DINNER * DCONV, conv_b + lyr * DINNER);

        // x_proj -> dbc fp32 + dbc16
        hgemm<0,true,true><<<dim3(NTOK / 128, 1), 256, HGEMM_SMEM>>>(
            p_xc16, DINNER, p_w16 + WX_OFF + (size_t)lyr * DBCW * DINNER,
            p_dbc, p_dbc16, DBCW, DBCW, DINNER, nullptr);

        // dt_proj + softplus -> delta fp32
        hgemm<2,true,false><<<dim3(NTOK / 128, DINNER / 128), 256, HGEMM_SMEM>>>(
            p_dbc16, DBCW, p_w16 + WDT_OFF + (size_t)lyr * DINNER * DTRANK,
            p_delta, nullptr, DINNER, DINNER, DTRANK, bdt + lyr * DINNER);

        // selective scan -> y16
        scan_kernel<<<(BATCH * DINNER) / 8, 256>>>(lyr, Dv + lyr * DINNER);

        // out_proj -> gout fp32
        hgemm<0,true,false><<<dim3(NTOK / 128, DMODEL / 128), 256, HGEMM_SMEM>>>(
            p_y16, DINNER, p_w16 + WO_OFF + (size_t)lyr * DMODEL * DINNER,
            p_gout, nullptr, DMODEL, DMODEL, DINNER, nullptr);

        // layernorm -> h fp32 + h16
        ln_kernel<<<NTOK * 32 / 256, 256>>>(ln_g + lyr * DMODEL, ln_b + lyr * DMODEL);
    }

    pool_kernel<<<BATCH, DMODEL>>>();
    head_kernel<<<(BATCH * NCLASSES + 255) / 256, 256>>>(Wout, bout, out);
}

// round 7
// speedup vs baseline: 1.5189x; 1.0043x over previous
#include <cuda_runtime.h>
#include <cuda_fp16.h>
#include <math.h>
#include <stdint.h>

// ---------------- problem constants ----------------
#define BATCH    8
#define LSEQ     1024
#define DMODEL   512
#define DINNER   1024
#define DSTATE   32
#define DCONV    4
#define DTRANK   32
#define NLAYERS  2
#define NMELS    128
#define NCLASSES 1251
#define NTOK     (BATCH*LSEQ)
#define DBCW     (DTRANK + 2*DSTATE) // 96

// fp16 weight arena offsets (in halves)
#define WP_OFF  0
#define WP_SZ   (DMODEL*NMELS)
#define WI_OFF  (WP_OFF + WP_SZ)
#define WI_SZ   (NLAYERS*2*DINNER*DMODEL)
#define WX_OFF  (WI_OFF + WI_SZ)
#define WX_SZ   (NLAYERS*DBCW*DINNER)
#define WDT_OFF (WX_OFF + WX_SZ)
#define WDT_SZ  (NLAYERS*DINNER*DTRANK)
#define WO_OFF  (WDT_OFF + WDT_SZ)
#define WO_SZ   (NLAYERS*DMODEL*DINNER)
#define W16_TOTAL (WO_OFF + WO_SZ)
#define X16_SZ  (NTOK*NMELS)

// ---------------- scratch ----------------
__device__ float  g_h    [NTOK * DMODEL];
__device__ float  g_xz   [NTOK * 2 * DINNER];
__device__ float  g_xc   [NTOK * DINNER];
__device__ float  g_dbc  [NTOK * DBCW];
__device__ float  g_delta[NTOK * DINNER];
__device__ float  g_gout [NTOK * DMODEL];
__device__ float  g_A2   [NLAYERS * DINNER * DSTATE];
__device__ float  g_pool [BATCH * DMODEL];
__device__ __half g_w16  [W16_TOTAL];
__device__ __half g_x16  [X16_SZ];
__device__ __half g_h16  [NTOK * DMODEL];
__device__ __half g_xc16 [NTOK * DINNER];
__device__ __half g_dbc16[NTOK * DBCW];
__device__ __half g_y16  [NTOK * DINNER];

// ---------------- scalar helpers ----------------
__device__ __forceinline__ float ex2f(float x) {
    float y; asm("ex2.approx.ftz.f32 %0, %1;" : "=f"(y) : "f"(x)); return y;
}
__device__ __forceinline__ float softplus_f(float x) {
    return (x > 20.f) ? x : log1pf(expf(x));
}
__device__ __forceinline__ float silu_f(float x) {
    return x / (1.f + expf(-x));
}
__device__ __forceinline__ uint32_t smem_to_u32(const void* p) {
    uint32_t a;
    asm("{ .reg .u64 t; cvta.to.shared.u64 t, %1; cvt.u32.u64 %0, t; }"
        : "=r"(a) : "l"(p));
    return a;
}

// ---------------- mma / ldmatrix / cp.async primitives ----------------
__device__ __forceinline__ void ldsm_x4(uint32_t* r, uint32_t addr) {
    asm volatile(
        "ldmatrix.sync.aligned.m8n8.x4.shared.b16 {%0,%1,%2,%3}, [%4];"
        : "=r"(r[0]), "=r"(r[1]), "=r"(r[2]), "=r"(r[3]) : "r"(addr));
}
__device__ __forceinline__ void mma_f16(
    float& c0, float& c1, float& c2, float& c3,
    uint32_t a0, uint32_t a1, uint32_t a2, uint32_t a3,
    uint32_t b0, uint32_t b1)
{
    asm volatile(
        "mma.sync.aligned.m16n8k16.row.col.f32.f16.f16.f32 "
        "{%0,%1,%2,%3}, {%4,%5,%6,%7}, {%8,%9}, {%0,%1,%2,%3};"
        : "+f"(c0), "+f"(c1), "+f"(c2), "+f"(c3)
        : "r"(a0), "r"(a1), "r"(a2), "r"(a3), "r"(b0), "r"(b1));
}
__device__ __forceinline__ void cpa16(uint32_t dst, const void* src, uint32_t sz) {
    asm volatile("cp.async.cg.shared.global [%0], [%1], 16, %2;"
                 :: "r"(dst), "l"(src), "r"(sz) : "memory");
}
__device__ __forceinline__ void cpa_commit() {
    asm volatile("cp.async.commit_group;" ::: "memory");
}
__device__ __forceinline__ void cpa_wait(int rem) {
    if (rem == 0)      asm volatile("cp.async.wait_group 0;" ::: "memory");
    else if (rem == 1) asm volatile("cp.async.wait_group 1;" ::: "memory");
    else               asm volatile("cp.async.wait_group 2;" ::: "memory");
}

// ---------------- fp16 tensor-core GEMM, cp.async 3-stage (unchanged R6) ----
#define HGEMM_SMEM (128 + 3*32768)

__device__ __forceinline__ void stage_async(
    const __half* __restrict__ G, int ldg, int rows_valid, int K, int k0,
    uint32_t sbuf, int tid)
{
#pragma unroll
    for (int i = 0; i < 4; i++) {
        int id  = tid + i * 256;
        int row = id >> 3;
        int ch  = id & 7;
        int k   = k0 + ch * 8;
        uint32_t sz = (row < rows_valid && k < K) ? 16u : 0u;
        const void* src = G + (size_t)row * ldg + k;
        uint32_t dst = sbuf + row * 128 + ((ch * 16) ^ ((row & 7) << 4));
        cpa16(dst, src, sz);
    }
}

template<int EPI, bool WF, bool WH>
__global__ __launch_bounds__(256) void hgemm(
    const __half* __restrict__ A, int lda,
    const __half* __restrict__ W,
    float* __restrict__ Cf, __half* __restrict__ Ch, int ldc,
    int N, int K,
    const float* __restrict__ bias)
{
    extern __shared__ char sm[];
    uint32_t raw  = smem_to_u32(sm);
    uint32_t base = (raw + 127u) & ~127u;

    const int tid  = threadIdx.x;
    const int wid  = tid >> 5;
    const int lane = tid & 31;
    const int wm = wid & 3;
    const int wn = wid >> 2;
    const int g  = lane >> 2;
    const int tg = lane & 3;
    const int m0 = blockIdx.x * 128;
    const int n0 = blockIdx.y * 128;

    const __half* Ab = A + (size_t)m0 * lda;
    const __half* Wb = W + (size_t)n0 * K;
    int nB = N - n0; if (nB > 128) nB = 128;

    float acc[2][8][4];
#pragma unroll
    for (int i = 0; i < 2; i++)
#pragma unroll
        for (int j = 0; j < 8; j++)
#pragma unroll
            for (int c = 0; c < 4; c++) acc[i][j][c] = 0.f;

    const int T = (K + 63) / 64;

#pragma unroll
    for (int s = 0; s < 3; s++) {
        if (s < T) {
            stage_async(Ab, lda, 128, K, s * 64, base + s * 32768,           tid);
            stage_async(Wb, K,   nB,  K, s * 64, base + s * 32768 + 16384u,  tid);
            cpa_commit();
        }
    }

    const int a_lrow = lane & 15;
    const int a_ksel = (lane >> 4) << 4;
    const int b_nofs = (((lane >> 4) & 1) << 3) + (lane & 7);
    const int b_ksel = ((lane >> 3) & 1) << 4;

    for (int t = 0; t < T; t++) {
        int rem = T - 1 - t; if (rem > 2) rem = 2;
        cpa_wait(rem);
        __syncthreads();

        const int buf = t % 3;
        const uint32_t abase = base + buf * 32768u;
        const uint32_t bbase = abase + 16384u;

#pragma unroll
        for (int k16 = 0; k16 < 4; k16++) {
            const uint32_t kb = k16 * 32;
            uint32_t af[2][4];
#pragma unroll
            for (int i = 0; i < 2; i++) {
                int row = wm * 32 + i * 16 + a_lrow;
                ldsm_x4(af[i], abase + row * 128
                               + ((kb + a_ksel) ^ ((row & 7) << 4)));
            }
            uint32_t bf[4][4];
#pragma unroll
            for (int p = 0; p < 4; p++) {
                int row = wn * 64 + p * 16 + b_nofs;
                ldsm_x4(bf[p], bbase + row * 128
                               + ((kb + b_ksel) ^ ((row & 7) << 4)));
            }
#pragma unroll
            for (int i = 0; i < 2; i++)
#pragma unroll
                for (int p = 0; p < 4; p++) {
                    mma_f16(acc[i][2*p][0], acc[i][2*p][1],
                            acc[i][2*p][2], acc[i][2*p][3],
                            af[i][0], af[i][1], af[i][2], af[i][3],
                            bf[p][0], bf[p][1]);
                    mma_f16(acc[i][2*p+1][0], acc[i][2*p+1][1],
                            acc[i][2*p+1][2], acc[i][2*p+1][3],
                            af[i][0], af[i][1], af[i][2], af[i][3],
                            bf[p][2], bf[p][3]);
                }
        }
        __syncthreads();
        if (t + 3 < T) {
            stage_async(Ab, lda, 128, K, (t + 3) * 64, base + buf * 32768u,          tid);
            stage_async(Wb, K,   nB,  K, (t + 3) * 64, base + buf * 32768u + 16384u, tid);
            cpa_commit();
        }
    }

#pragma unroll
    for (int i = 0; i < 2; i++) {
#pragma unroll
        for (int j = 0; j < 8; j++) {
            int row = m0 + wm * 32 + i * 16 + g;
            int col = n0 + wn * 64 + j * 8 + tg * 2;
            if (col < N) {
                float b0 = 0.f, b1 = 0.f;
                if (EPI >= 1) { b0 = bias[col]; b1 = bias[col + 1]; }
                float v0 = acc[i][j][0] + b0, v1 = acc[i][j][1] + b1;
                float v2 = acc[i][j][2] + b0, v3 = acc[i][j][3] + b1;
                if (EPI == 2) {
                    v0 = softplus_f(v0); v1 = softplus_f(v1);
                    v2 = softplus_f(v2); v3 = softplus_f(v3);
                }
                if (WF) {
                    *reinterpret_cast<float2*>(Cf + (size_t)row * ldc + col)
                        = make_float2(v0, v1);
                    *reinterpret_cast<float2*>(Cf + (size_t)(row + 8) * ldc + col)
                        = make_float2(v2, v3);
                }
                if (WH) {
                    *reinterpret_cast<__half2*>(Ch + (size_t)row * ldc + col)
                        = __floats2half2_rn(v0, v1);
                    *reinterpret_cast<__half2*>(Ch + (size_t)(row + 8) * ldc + col)
                        = __floats2half2_rn(v2, v3);
                }
            }
        }
    }
}

// ---------------- fp16 conversion of all weights + x ----------------
__global__ void wcvt_kernel(
    const float* __restrict__ Wp, const float* __restrict__ Wi,
    const float* __restrict__ Wx, const float* __restrict__ Wdt,
    const float* __restrict__ Wo, const float* __restrict__ x)
{
    int i = blockIdx.x * blockDim.x + threadIdx.x;
    const int C0 = WP_SZ, C1 = C0 + WI_SZ, C2 = C1 + WX_SZ,
              C3 = C2 + WDT_SZ, C4 = C3 + WO_SZ, C5 = C4 + X16_SZ;
    if (i >= C5) return;
    float v; __half* dst;
    if (i < C0)      { v = Wp[i];        dst = g_w16 + WP_OFF  + i; }
    else if (i < C1) { v = Wi[i - C0];   dst = g_w16 + WI_OFF  + (i - C0); }
    else if (i < C2) { v = Wx[i - C1];   dst = g_w16 + WX_OFF  + (i - C1); }
    else if (i < C3) { v = Wdt[i - C2];  dst = g_w16 + WDT_OFF + (i - C2); }
    else if (i < C4) { v = Wo[i - C3];   dst = g_w16 + WO_OFF  + (i - C3); }
    else             { v = x[i - C4];    dst = g_x16 + (i - C4); }
    *dst = __float2half_rn(v);
}

// ---------------- A2 precompute ----------------
__global__ void a2_kernel(const float* __restrict__ A_log) {
    int i = blockIdx.x * blockDim.x + threadIdx.x;
    if (i < NLAYERS * DINNER * DSTATE)
        g_A2[i] = -expf(A_log[i]) * 1.4426950408889634f;
}

// ---------------- causal depthwise conv1d + bias + silu ----------------
__global__ __launch_bounds__(256) void conv_kernel(
    const float* __restrict__ cw, const float* __restrict__ cb)
{
    int idx = blockIdx.x * blockDim.x + threadIdx.x;
    int d  = idx & (DINNER - 1);
    int r  = idx >> 10;
    int lg = r & (LSEQ / 4 - 1);
    int b  = r >> 8;
    int l0 = lg * 4;
    int t0 = b * LSEQ + l0;
    const float* base = g_xz + (size_t)t0 * (2 * DINNER) + d;
    float v[7];
#pragma unroll
    for (int i = 0; i < 7; i++) {
        int l = l0 - 3 + i;
        v[i] = (l >= 0) ? base[(i - 3) * (2 * DINNER)] : 0.f;
    }
    float4 w = *reinterpret_cast<const float4*>(cw + d * 4);
    float bias = cb[d];
    float*  o   = g_xc   + (size_t)t0 * DINNER + d;
    __half* o16 = g_xc16 + (size_t)t0 * DINNER + d;
#pragma unroll
    for (int j = 0; j < 4; j++) {
        float acc = bias;
        acc = fmaf(w.x, v[j],     acc);
        acc = fmaf(w.y, v[j + 1], acc);
        acc = fmaf(w.z, v[j + 2], acc);
        acc = fmaf(w.w, v[j + 3], acc);
        float s = silu_f(acc);
        o[j * DINNER]   = s;
        o16[j * DINNER] = __float2half_rn(s);
    }
}

// ---------------- selective scan v2: 4 channels/warp, 8 lanes x 4 states ----
// lane = ch*8 + sg; lane keeps states sg*4..sg*4+3 of channel (dbase+ch).
// Per step: 1 warp-LDG each for dlt/u (4 addrs), float4 B, float4 C;
// 3-shfl reduce within 8-lane groups; sg==0 lanes gate+store.
__global__ __launch_bounds__(256) void scan_kernel(
    int layer, const float* __restrict__ Dvec)
{
    int w    = (blockIdx.x * blockDim.x + threadIdx.x) >> 5;  // 0..2047
    int lane = threadIdx.x & 31;
    int ch   = lane >> 3;
    int sg   = lane & 7;
    int b     = w >> 8;                  // 2048 warps / 256 per batch
    int dbase = (w & 255) * 4;
    int d     = dbase + ch;

    const float* dp = g_delta + (size_t)(b * LSEQ) * DINNER + d;
    const float* up = g_xc    + (size_t)(b * LSEQ) * DINNER + d;
    const float* rp = g_xz    + (size_t)(b * LSEQ) * (2 * DINNER) + DINNER + d;
    const float* Bp = g_dbc   + (size_t)(b * LSEQ) * DBCW + DTRANK + sg * 4;
    __half*      yp = g_y16   + (size_t)(b * LSEQ) * DINNER + d;

    float4 a2 = *reinterpret_cast<const float4*>(
        g_A2 + (size_t)(layer * DINNER + d) * DSTATE + sg * 4);
    float Dd = Dvec[d];
    float h0 = 0.f, h1 = 0.f, h2 = 0.f, h3 = 0.f;

#pragma unroll 4
    for (int l = 0; l < LSEQ; l++) {
        float dlt  = __ldg(dp);
        float u    = __ldg(up);
        float4 Bv  = *reinterpret_cast<const float4*>(Bp);
        float4 Cv  = *reinterpret_cast<const float4*>(Bp + DSTATE);
        float du   = dlt * u;
        h0 = fmaf(ex2f(dlt * a2.x), h0, du * Bv.x);
        h1 = fmaf(ex2f(dlt * a2.y), h1, du * Bv.y);
        h2 = fmaf(ex2f(dlt * a2.z), h2, du * Bv.z);
        h3 = fmaf(ex2f(dlt * a2.w), h3, du * Bv.w);
        float py = h0 * Cv.x;
        py = fmaf(h1, Cv.y, py);
        py = fmaf(h2, Cv.z, py);
        py = fmaf(h3, Cv.w, py);
        py += __shfl_xor_sync(0xffffffffu, py, 1);
        py += __shfl_xor_sync(0xffffffffu, py, 2);
        py += __shfl_xor_sync(0xffffffffu, py, 4);
        if (sg == 0) {
            float r = *rp;
            *yp = __float2half_rn((py + u * Dd) * silu_f(r));
        }
        dp += DINNER; up += DINNER; Bp += DBCW;
        rp += 2 * DINNER; yp += DINNER;
    }
}

// ---------------- LayerNorm (fp32 + fp16 out) ----------------
__global__ __launch_bounds__(256) void ln_kernel(
    const float* __restrict__ gam, const float* __restrict__ bet)
{
    int warp = (blockIdx.x * blockDim.x + threadIdx.x) >> 5;
    int lane = threadIdx.x & 31;
    const float* row = g_gout + (size_t)warp * DMODEL;
    float v[16];
#pragma unroll
    for (int i = 0; i < 4; i++) {
        float4 t = *reinterpret_cast<const float4*>(&row[lane * 4 + i * 128]);
        v[i * 4 + 0] = t.x; v[i * 4 + 1] = t.y; v[i * 4 + 2] = t.z; v[i * 4 + 3] = t.w;
    }
    float s = 0.f;
#pragma unroll
    for (int i = 0; i < 16; i++) s += v[i];
#pragma unroll
    for (int o = 16; o > 0; o >>= 1) s += __shfl_xor_sync(0xffffffffu, s, o);
    float mu = s * (1.f / DMODEL);
    float q = 0.f;
#pragma unroll
    for (int i = 0; i < 16; i++) { float e = v[i] - mu; q = fmaf(e, e, q); }
#pragma unroll
    for (int o = 16; o > 0; o >>= 1) q += __shfl_xor_sync(0xffffffffu, q, o);
    float rs = rsqrtf(q * (1.f / DMODEL) + 1e-5f);
    float*  orow  = g_h   + (size_t)warp * DMODEL;
    __half* orow16= g_h16 + (size_t)warp * DMODEL;
#pragma unroll
    for (int i = 0; i < 4; i++) {
        int c = lane * 4 + i * 128;
        float4 gg = *reinterpret_cast<const float4*>(&gam[c]);
        float4 bb = *reinterpret_cast<const float4*>(&bet[c]);
        float4 o;
        o.x = (v[i*4+0] - mu) * rs * gg.x + bb.x;
        o.y = (v[i*4+1] - mu) * rs * gg.y + bb.y;
        o.z = (v[i*4+2] - mu) * rs * gg.z + bb.z;
        o.w = (v[i*4+3] - mu) * rs * gg.w + bb.w;
        *reinterpret_cast<float4*>(&orow[c]) = o;
        *reinterpret_cast<__half2*>(&orow16[c])     = __floats2half2_rn(o.x, o.y);
        *reinterpret_cast<__half2*>(&orow16[c + 2]) = __floats2half2_rn(o.z, o.w);
    }
}

// ---------------- mean pool ----------------
__global__ void pool_kernel() {
    int b = blockIdx.x;
    int c = threadIdx.x;
    float s = 0.f;
    for (int l = 0; l < LSEQ; l++)
        s += g_h[(size_t)(b * LSEQ + l) * DMODEL + c];
    g_pool[b * DMODEL + c] = s * (1.f / LSEQ);
}

// ---------------- classifier head ----------------
__global__ void head_kernel(const float* __restrict__ Wout,
                            const float* __restrict__ bout,
                            float* __restrict__ out)
{
    int idx = blockIdx.x * blockDim.x + threadIdx.x;
    if (idx >= BATCH * NCLASSES) return;
    int m = idx / NCLASSES, n = idx % NCLASSES;
    const float* p = g_pool + m * DMODEL;
    const float* wr = Wout + (size_t)n * DMODEL;
    float s = bout[n];
    for (int k = 0; k < DMODEL; k += 4) {
        float4 a = *reinterpret_cast<const float4*>(p + k);
        float4 w = *reinterpret_cast<const float4*>(wr + k);
        s = fmaf(a.x, w.x, s); s = fmaf(a.y, w.y, s);
        s = fmaf(a.z, w.z, s); s = fmaf(a.w, w.w, s);
    }
    out[idx] = s;
}

// ---------------- launcher ----------------
extern "C" void kernel_launch(void* const* d_in, const int* in_sizes, int n_in,
                              void* d_out, int out_size)
{
    const float* x      = (const float*)d_in[0];
    const float* Wp     = (const float*)d_in[1];
    const float* bp     = (const float*)d_in[2];
    const float* Wi     = (const float*)d_in[3];
    const float* conv_w = (const float*)d_in[4];
    const float* conv_b = (const float*)d_in[5];
    const float* Wx     = (const float*)d_in[6];
    const float* Wdt    = (const float*)d_in[7];
    const float* bdt    = (const float*)d_in[8];
    const float* A_log  = (const float*)d_in[9];
    const float* Dv     = (const float*)d_in[10];
    const float* Wo     = (const float*)d_in[11];
    const float* ln_g   = (const float*)d_in[12];
    const float* ln_b   = (const float*)d_in[13];
    const float* Wout   = (const float*)d_in[14];
    const float* bout   = (const float*)d_in[15];
    float* out = (float*)d_out;

    float *p_xz, *p_dbc, *p_delta, *p_gout;
    __half *p_w16, *p_x16, *p_h16, *p_xc16, *p_dbc16, *p_y16;
    cudaGetSymbolAddress((void**)&p_xz,    g_xz);
    cudaGetSymbolAddress((void**)&p_dbc,   g_dbc);
    cudaGetSymbolAddress((void**)&p_delta, g_delta);
    cudaGetSymbolAddress((void**)&p_gout,  g_gout);
    cudaGetSymbolAddress((void**)&p_w16,   g_w16);
    cudaGetSymbolAddress((void**)&p_x16,   g_x16);
    cudaGetSymbolAddress((void**)&p_h16,   g_h16);
    cudaGetSymbolAddress((void**)&p_xc16,  g_xc16);
    cudaGetSymbolAddress((void**)&p_dbc16, g_dbc16);
    cudaGetSymbolAddress((void**)&p_y16,   g_y16);

    cudaFuncSetAttribute(hgemm<1,false,true>, cudaFuncAttributeMaxDynamicSharedMemorySize, HGEMM_SMEM);
    cudaFuncSetAttribute(hgemm<0,true,false>, cudaFuncAttributeMaxDynamicSharedMemorySize, HGEMM_SMEM);
    cudaFuncSetAttribute(hgemm<0,true,true>,  cudaFuncAttributeMaxDynamicSharedMemorySize, HGEMM_SMEM);
    cudaFuncSetAttribute(hgemm<2,true,false>, cudaFuncAttributeMaxDynamicSharedMemorySize, HGEMM_SMEM);

    {
        int total = WP_SZ + WI_SZ + WX_SZ + WDT_SZ + WO_SZ + X16_SZ;
        wcvt_kernel<<<(total + 255) / 256, 256>>>(Wp, Wi, Wx, Wdt, Wo, x);
    }
    a2_kernel<<<(NLAYERS * DINNER * DSTATE + 255) / 256, 256>>>(A_log);

    hgemm<1,false,true><<<dim3(NTOK / 128, DMODEL / 128), 256, HGEMM_SMEM>>>(
        p_x16, NMELS, p_w16 + WP_OFF, nullptr, p_h16, DMODEL, DMODEL, NMELS, bp);

    for (int lyr = 0; lyr < NLAYERS; lyr++) {
        hgemm<0,true,false><<<dim3(NTOK / 128, (2 * DINNER) / 128), 256, HGEMM_SMEM>>>(
            p_h16, DMODEL, p_w16 + WI_OFF + (size_t)lyr * 2 * DINNER * DMODEL,
            p_xz, nullptr, 2 * DINNER, 2 * DINNER, DMODEL, nullptr);

        conv_kernel<<<(NTOK * DINNER / 4) / 256, 256>>>(
            conv_w + lyr * DINNER * DCONV, conv_b + lyr * DINNER);

        hgemm<0,true,true><<<dim3(NTOK / 128, 1), 256, HGEMM_SMEM>>>(
            p_xc16, DINNER, p_w16 + WX_OFF + (size_t)lyr * DBCW * DINNER,
            p_dbc, p_dbc16, DBCW, DBCW, DINNER, nullptr);

        hgemm<2,true,false><<<dim3(NTOK / 128, DINNER / 128), 256, HGEMM_SMEM>>>(
            p_dbc16, DBCW, p_w16 + WDT_OFF + (size_t)lyr * DINNER * DTRANK,
            p_delta, nullptr, DINNER, DINNER, DTRANK, bdt + lyr * DINNER);

        // scan v2: 4 channels/warp -> 2048 warps -> 256 blocks of 8 warps
        scan_kernel<<<(BATCH * DINNER / 4) / 8, 256>>>(lyr, Dv + lyr * DINNER);

        hgemm<0,true,false><<<dim3(NTOK / 128, DMODEL / 128), 256, HGEMM_SMEM>>>(
            p_y16, DINNER, p_w16 + WO_OFF + (size_t)lyr * DMODEL * DINNER,
            p_gout, nullptr, DMODEL, DMODEL, DINNER, nullptr);

        ln_kernel<<<NTOK * 32 / 256, 256>>>(ln_g + lyr * DMODEL, ln_b + lyr * DMODEL);
    }

    pool_kernel<<<BATCH, DMODEL>>>();
    head_kernel<<<(BATCH * NCLASSES + 255) / 256, 256>>>(Wout, bout, out);
}

// round 8
// speedup vs baseline: 4.7341x; 3.1168x over previous
#include <cuda_runtime.h>
#include <cuda_fp16.h>
#include <math.h>
#include <stdint.h>

// ---------------- problem constants ----------------
#define BATCH    8
#define LSEQ     1024
#define DMODEL   512
#define DINNER   1024
#define DSTATE   32
#define DCONV    4
#define DTRANK   32
#define NLAYERS  2
#define NMELS    128
#define NCLASSES 1251
#define NTOK     (BATCH*LSEQ)
#define DBCW     (DTRANK + 2*DSTATE) // 96

// fp16 weight arena offsets (in halves)
#define WP_OFF  0
#define WP_SZ   (DMODEL*NMELS)
#define WI_OFF  (WP_OFF + WP_SZ)
#define WI_SZ   (NLAYERS*2*DINNER*DMODEL)
#define WX_OFF  (WI_OFF + WI_SZ)
#define WX_SZ   (NLAYERS*DBCW*DINNER)
#define WDT_OFF (WX_OFF + WX_SZ)
#define WDT_SZ  (NLAYERS*DINNER*DTRANK)
#define WO_OFF  (WDT_OFF + WDT_SZ)
#define WO_SZ   (NLAYERS*DMODEL*DINNER)
#define W16_TOTAL (WO_OFF + WO_SZ)
#define X16_SZ  (NTOK*NMELS)

#define POOL_SEGS 4

// ---------------- scratch ----------------
__device__ float  g_h    [NTOK * DMODEL];
__device__ float  g_xz   [NTOK * 2 * DINNER];
__device__ float  g_xc   [NTOK * DINNER];
__device__ float  g_dbc  [NTOK * DBCW];
__device__ float  g_delta[NTOK * DINNER];
__device__ float  g_gout [NTOK * DMODEL];
__device__ float  g_A2   [NLAYERS * DINNER * DSTATE];
__device__ float  g_pool [BATCH * DMODEL];
__device__ float  g_poolp[BATCH * POOL_SEGS * DMODEL];
__device__ __half g_w16  [W16_TOTAL];
__device__ __half g_x16  [X16_SZ];
__device__ __half g_h16  [NTOK * DMODEL];
__device__ __half g_xc16 [NTOK * DINNER];
__device__ __half g_dbc16[NTOK * DBCW];
__device__ __half g_y16  [NTOK * DINNER];

// ---------------- scalar helpers ----------------
__device__ __forceinline__ float ex2f(float x) {
    float y; asm("ex2.approx.ftz.f32 %0, %1;" : "=f"(y) : "f"(x)); return y;
}
__device__ __forceinline__ float softplus_f(float x) {
    return (x > 20.f) ? x : log1pf(expf(x));
}
__device__ __forceinline__ float silu_f(float x) {
    return x / (1.f + expf(-x));
}
__device__ __forceinline__ uint32_t smem_to_u32(const void* p) {
    uint32_t a;
    asm("{ .reg .u64 t; cvta.to.shared.u64 t, %1; cvt.u32.u64 %0, t; }"
        : "=r"(a) : "l"(p));
    return a;
}

// ---------------- mma / ldmatrix / cp.async primitives ----------------
__device__ __forceinline__ void ldsm_x4(uint32_t* r, uint32_t addr) {
    asm volatile(
        "ldmatrix.sync.aligned.m8n8.x4.shared.b16 {%0,%1,%2,%3}, [%4];"
        : "=r"(r[0]), "=r"(r[1]), "=r"(r[2]), "=r"(r[3]) : "r"(addr));
}
__device__ __forceinline__ void mma_f16(
    float& c0, float& c1, float& c2, float& c3,
    uint32_t a0, uint32_t a1, uint32_t a2, uint32_t a3,
    uint32_t b0, uint32_t b1)
{
    asm volatile(
        "mma.sync.aligned.m16n8k16.row.col.f32.f16.f16.f32 "
        "{%0,%1,%2,%3}, {%4,%5,%6,%7}, {%8,%9}, {%0,%1,%2,%3};"
        : "+f"(c0), "+f"(c1), "+f"(c2), "+f"(c3)
        : "r"(a0), "r"(a1), "r"(a2), "r"(a3), "r"(b0), "r"(b1));
}
__device__ __forceinline__ void cpa16(uint32_t dst, const void* src, uint32_t sz) {
    asm volatile("cp.async.cg.shared.global [%0], [%1], 16, %2;"
                 :: "r"(dst), "l"(src), "r"(sz) : "memory");
}
__device__ __forceinline__ void cpa16u(uint32_t dst, const void* src) {
    asm volatile("cp.async.cg.shared.global [%0], [%1], 16;"
                 :: "r"(dst), "l"(src) : "memory");
}
__device__ __forceinline__ void cpa_commit() {
    asm volatile("cp.async.commit_group;" ::: "memory");
}
__device__ __forceinline__ void cpa_wait(int rem) {
    if (rem == 0)      asm volatile("cp.async.wait_group 0;" ::: "memory");
    else if (rem == 1) asm volatile("cp.async.wait_group 1;" ::: "memory");
    else               asm volatile("cp.async.wait_group 2;" ::: "memory");
}

// ---------------- fp16 tensor-core GEMM, cp.async 3-stage (unchanged) ----
#define HGEMM_SMEM (128 + 3*32768)

__device__ __forceinline__ void stage_async(
    const __half* __restrict__ G, int ldg, int rows_valid, int K, int k0,
    uint32_t sbuf, int tid)
{
#pragma unroll
    for (int i = 0; i < 4; i++) {
        int id  = tid + i * 256;
        int row = id >> 3;
        int ch  = id & 7;
        int k   = k0 + ch * 8;
        uint32_t sz = (row < rows_valid && k < K) ? 16u : 0u;
        const void* src = G + (size_t)row * ldg + k;
        uint32_t dst = sbuf + row * 128 + ((ch * 16) ^ ((row & 7) << 4));
        cpa16(dst, src, sz);
    }
}

template<int EPI, bool WF, bool WH>
__global__ __launch_bounds__(256) void hgemm(
    const __half* __restrict__ A, int lda,
    const __half* __restrict__ W,
    float* __restrict__ Cf, __half* __restrict__ Ch, int ldc,
    int N, int K,
    const float* __restrict__ bias)
{
    extern __shared__ char sm[];
    uint32_t raw  = smem_to_u32(sm);
    uint32_t base = (raw + 127u) & ~127u;

    const int tid  = threadIdx.x;
    const int wid  = tid >> 5;
    const int lane = tid & 31;
    const int wm = wid & 3;
    const int wn = wid >> 2;
    const int g  = lane >> 2;
    const int tg = lane & 3;
    const int m0 = blockIdx.x * 128;
    const int n0 = blockIdx.y * 128;

    const __half* Ab = A + (size_t)m0 * lda;
    const __half* Wb = W + (size_t)n0 * K;
    int nB = N - n0; if (nB > 128) nB = 128;

    float acc[2][8][4];
#pragma unroll
    for (int i = 0; i < 2; i++)
#pragma unroll
        for (int j = 0; j < 8; j++)
#pragma unroll
            for (int c = 0; c < 4; c++) acc[i][j][c] = 0.f;

    const int T = (K + 63) / 64;

#pragma unroll
    for (int s = 0; s < 3; s++) {
        if (s < T) {
            stage_async(Ab, lda, 128, K, s * 64, base + s * 32768,           tid);
            stage_async(Wb, K,   nB,  K, s * 64, base + s * 32768 + 16384u,  tid);
            cpa_commit();
        }
    }

    const int a_lrow = lane & 15;
    const int a_ksel = (lane >> 4) << 4;
    const int b_nofs = (((lane >> 4) & 1) << 3) + (lane & 7);
    const int b_ksel = ((lane >> 3) & 1) << 4;

    for (int t = 0; t < T; t++) {
        int rem = T - 1 - t; if (rem > 2) rem = 2;
        cpa_wait(rem);
        __syncthreads();

        const int buf = t % 3;
        const uint32_t abase = base + buf * 32768u;
        const uint32_t bbase = abase + 16384u;

#pragma unroll
        for (int k16 = 0; k16 < 4; k16++) {
            const uint32_t kb = k16 * 32;
            uint32_t af[2][4];
#pragma unroll
            for (int i = 0; i < 2; i++) {
                int row = wm * 32 + i * 16 + a_lrow;
                ldsm_x4(af[i], abase + row * 128
                               + ((kb + a_ksel) ^ ((row & 7) << 4)));
            }
            uint32_t bf[4][4];
#pragma unroll
            for (int p = 0; p < 4; p++) {
                int row = wn * 64 + p * 16 + b_nofs;
                ldsm_x4(bf[p], bbase + row * 128
                               + ((kb + b_ksel) ^ ((row & 7) << 4)));
            }
#pragma unroll
            for (int i = 0; i < 2; i++)
#pragma unroll
                for (int p = 0; p < 4; p++) {
                    mma_f16(acc[i][2*p][0], acc[i][2*p][1],
                            acc[i][2*p][2], acc[i][2*p][3],
                            af[i][0], af[i][1], af[i][2], af[i][3],
                            bf[p][0], bf[p][1]);
                    mma_f16(acc[i][2*p+1][0], acc[i][2*p+1][1],
                            acc[i][2*p+1][2], acc[i][2*p+1][3],
                            af[i][0], af[i][1], af[i][2], af[i][3],
                            bf[p][2], bf[p][3]);
                }
        }
        __syncthreads();
        if (t + 3 < T) {
            stage_async(Ab, lda, 128, K, (t + 3) * 64, base + buf * 32768u,          tid);
            stage_async(Wb, K,   nB,  K, (t + 3) * 64, base + buf * 32768u + 16384u, tid);
            cpa_commit();
        }
    }

#pragma unroll
    for (int i = 0; i < 2; i++) {
#pragma unroll
        for (int j = 0; j < 8; j++) {
            int row = m0 + wm * 32 + i * 16 + g;
            int col = n0 + wn * 64 + j * 8 + tg * 2;
            if (col < N) {
                float b0 = 0.f, b1 = 0.f;
                if (EPI >= 1) { b0 = bias[col]; b1 = bias[col + 1]; }
                float v0 = acc[i][j][0] + b0, v1 = acc[i][j][1] + b1;
                float v2 = acc[i][j][2] + b0, v3 = acc[i][j][3] + b1;
                if (EPI == 2) {
                    v0 = softplus_f(v0); v1 = softplus_f(v1);
                    v2 = softplus_f(v2); v3 = softplus_f(v3);
                }
                if (WF) {
                    *reinterpret_cast<float2*>(Cf + (size_t)row * ldc + col)
                        = make_float2(v0, v1);
                    *reinterpret_cast<float2*>(Cf + (size_t)(row + 8) * ldc + col)
                        = make_float2(v2, v3);
                }
                if (WH) {
                    *reinterpret_cast<__half2*>(Ch + (size_t)row * ldc + col)
                        = __floats2half2_rn(v0, v1);
                    *reinterpret_cast<__half2*>(Ch + (size_t)(row + 8) * ldc + col)
                        = __floats2half2_rn(v2, v3);
                }
            }
        }
    }
}

// ---------------- fp16 conversion of all weights + x ----------------
__global__ void wcvt_kernel(
    const float* __restrict__ Wp, const float* __restrict__ Wi,
    const float* __restrict__ Wx, const float* __restrict__ Wdt,
    const float* __restrict__ Wo, const float* __restrict__ x)
{
    int i = blockIdx.x * blockDim.x + threadIdx.x;
    const int C0 = WP_SZ, C1 = C0 + WI_SZ, C2 = C1 + WX_SZ,
              C3 = C2 + WDT_SZ, C4 = C3 + WO_SZ, C5 = C4 + X16_SZ;
    if (i >= C5) return;
    float v; __half* dst;
    if (i < C0)      { v = Wp[i];        dst = g_w16 + WP_OFF  + i; }
    else if (i < C1) { v = Wi[i - C0];   dst = g_w16 + WI_OFF  + (i - C0); }
    else if (i < C2) { v = Wx[i - C1];   dst = g_w16 + WX_OFF  + (i - C1); }
    else if (i < C3) { v = Wdt[i - C2];  dst = g_w16 + WDT_OFF + (i - C2); }
    else if (i < C4) { v = Wo[i - C3];   dst = g_w16 + WO_OFF  + (i - C3); }
    else             { v = x[i - C4];    dst = g_x16 + (i - C4); }
    *dst = __float2half_rn(v);
}

// ---------------- A2 precompute ----------------
__global__ void a2_kernel(const float* __restrict__ A_log) {
    int i = blockIdx.x * blockDim.x + threadIdx.x;
    if (i < NLAYERS * DINNER * DSTATE)
        g_A2[i] = -expf(A_log[i]) * 1.4426950408889634f;
}

// ---------------- causal depthwise conv1d + bias + silu ----------------
__global__ __launch_bounds__(256) void conv_kernel(
    const float* __restrict__ cw, const float* __restrict__ cb)
{
    int idx = blockIdx.x * blockDim.x + threadIdx.x;
    int d  = idx & (DINNER - 1);
    int r  = idx >> 10;
    int lg = r & (LSEQ / 4 - 1);
    int b  = r >> 8;
    int l0 = lg * 4;
    int t0 = b * LSEQ + l0;
    const float* base = g_xz + (size_t)t0 * (2 * DINNER) + d;
    float v[7];
#pragma unroll
    for (int i = 0; i < 7; i++) {
        int l = l0 - 3 + i;
        v[i] = (l >= 0) ? base[(i - 3) * (2 * DINNER)] : 0.f;
    }
    float4 w = *reinterpret_cast<const float4*>(cw + d * 4);
    float bias = cb[d];
    float*  o   = g_xc   + (size_t)t0 * DINNER + d;
    __half* o16 = g_xc16 + (size_t)t0 * DINNER + d;
#pragma unroll
    for (int j = 0; j < 4; j++) {
        float acc = bias;
        acc = fmaf(w.x, v[j],     acc);
        acc = fmaf(w.y, v[j + 1], acc);
        acc = fmaf(w.z, v[j + 2], acc);
        acc = fmaf(w.w, v[j + 3], acc);
        float s = silu_f(acc);
        o[j * DINNER]   = s;
        o16[j * DINNER] = __float2half_rn(s);
    }
}

// ---------------- selective scan v3: smem-staged, cp.async double-buffered ----
// Block = (batch b, 32-channel slice d0). 256 threads = 8 warps.
// Warp w handles channels d0 + w*4 + ch (ch = lane>>3); lane keeps 4 states
// (sg = lane&7 -> states sg*4..sg*4+3). 32-step chunks staged via cp.async:
//   delta/u/res rows are 128B contiguous per token for the slice;
//   B+C is one 256B contiguous segment per token. Recurrence runs from smem.
#define SCHUNK 32
#define NCHUNKS (LSEQ / SCHUNK)   // 32

__global__ __launch_bounds__(256) void scan_kernel(
    int layer, const float* __restrict__ Dvec)
{
    __shared__ float  s_dl[2][SCHUNK * 32];
    __shared__ float  s_u [2][SCHUNK * 32];
    __shared__ float  s_r [2][SCHUNK * 32];
    __shared__ float  s_bc[2][SCHUNK * 64];
    __shared__ __half s_y [SCHUNK * 32];

    const int tid  = threadIdx.x;
    const int wid  = tid >> 5;
    const int lane = tid & 31;
    const int ch   = lane >> 3;
    const int sg   = lane & 7;
    const int b    = blockIdx.x >> 5;          // 8 batches x 32 slices
    const int d0   = (blockIdx.x & 31) * 32;
    const int w4c  = wid * 4 + ch;             // channel within slice (0..31)
    const int d    = d0 + w4c;

    const uint32_t u_dl = smem_to_u32(s_dl);
    const uint32_t u_u  = smem_to_u32(s_u);
    const uint32_t u_r  = smem_to_u32(s_r);
    const uint32_t u_bc = smem_to_u32(s_bc);

    const float* gdl = g_delta + (size_t)(b * LSEQ) * DINNER + d0;
    const float* gu  = g_xc    + (size_t)(b * LSEQ) * DINNER + d0;
    const float* gr  = g_xz    + (size_t)(b * LSEQ) * (2 * DINNER) + DINNER + d0;
    const float* gbc = g_dbc   + (size_t)(b * LSEQ) * DBCW + DTRANK;

    // staging lambda-ish: chunk c into buffer c&1
    auto stage = [&](int c) {
        int buf = c & 1;
        int t0  = c * SCHUNK;
        {   // delta, u, res: 32 rows x 128B each; 256 cpa each -> 1 per thread
            int row = tid >> 3, seg = tid & 7;
            cpa16u(u_dl + (buf * SCHUNK * 32 + row * 32 + seg * 4) * 4,
                   gdl + (size_t)(t0 + row) * DINNER + seg * 4);
            cpa16u(u_u  + (buf * SCHUNK * 32 + row * 32 + seg * 4) * 4,
                   gu  + (size_t)(t0 + row) * DINNER + seg * 4);
            cpa16u(u_r  + (buf * SCHUNK * 32 + row * 32 + seg * 4) * 4,
                   gr  + (size_t)(t0 + row) * (2 * DINNER) + seg * 4);
        }
        {   // B+C: 32 rows x 256B = 512 cpa -> 2 per thread
#pragma unroll
            for (int i = 0; i < 2; i++) {
                int id = tid + i * 256;
                int row = id >> 4, seg = id & 15;
                cpa16u(u_bc + (buf * SCHUNK * 64 + row * 64 + seg * 4) * 4,
                       gbc + (size_t)(t0 + row) * DBCW + seg * 4);
            }
        }
        cpa_commit();
    };

    float4 a2 = *reinterpret_cast<const float4*>(
        g_A2 + ((size_t)(layer * DINNER + d)) * DSTATE + sg * 4);
    const float Dd = Dvec[d];
    float h0 = 0.f, h1 = 0.f, h2 = 0.f, h3 = 0.f;

    stage(0);
    stage(1);

    for (int c = 0; c < NCHUNKS; c++) {
        cpa_wait(c < NCHUNKS - 1 ? 1 : 0);
        __syncthreads();
        const int buf = c & 1;
        const float* dl = s_dl[buf];
        const float* uu = s_u[buf];
        const float* rr = s_r[buf];
        const float* bc = s_bc[buf];

#pragma unroll 4
        for (int l = 0; l < SCHUNK; l++) {
            float dlt = dl[l * 32 + w4c];
            float u   = uu[l * 32 + w4c];
            float4 Bv = *reinterpret_cast<const float4*>(bc + l * 64 + sg * 4);
            float4 Cv = *reinterpret_cast<const float4*>(bc + l * 64 + 32 + sg * 4);
            float du  = dlt * u;
            h0 = fmaf(ex2f(dlt * a2.x), h0, du * Bv.x);
            h1 = fmaf(ex2f(dlt * a2.y), h1, du * Bv.y);
            h2 = fmaf(ex2f(dlt * a2.z), h2, du * Bv.z);
            h3 = fmaf(ex2f(dlt * a2.w), h3, du * Bv.w);
            float py = h0 * Cv.x;
            py = fmaf(h1, Cv.y, py);
            py = fmaf(h2, Cv.z, py);
            py = fmaf(h3, Cv.w, py);
            py += __shfl_xor_sync(0xffffffffu, py, 1);
            py += __shfl_xor_sync(0xffffffffu, py, 2);
            py += __shfl_xor_sync(0xffffffffu, py, 4);
            if (sg == 0) {
                float r = rr[l * 32 + w4c];
                s_y[l * 32 + w4c] = __float2half_rn((py + u * Dd) * silu_f(r));
            }
        }
        __syncthreads();
        // flush y chunk: 32 rows x 64B = 128 uint4 stores
        if (tid < 128) {
            int row = tid >> 2, seg = tid & 3;
            *reinterpret_cast<uint4*>(
                g_y16 + (size_t)(b * LSEQ + c * SCHUNK + row) * DINNER
                      + d0 + seg * 8)
                = *reinterpret_cast<const uint4*>(s_y + row * 32 + seg * 8);
        }
        if (c + 2 < NCHUNKS) stage(c + 2);
    }
}

// ---------------- LayerNorm (fp32 + fp16 out) ----------------
__global__ __launch_bounds__(256) void ln_kernel(
    const float* __restrict__ gam, const float* __restrict__ bet)
{
    int warp = (blockIdx.x * blockDim.x + threadIdx.x) >> 5;
    int lane = threadIdx.x & 31;
    const float* row = g_gout + (size_t)warp * DMODEL;
    float v[16];
#pragma unroll
    for (int i = 0; i < 4; i++) {
        float4 t = *reinterpret_cast<const float4*>(&row[lane * 4 + i * 128]);
        v[i * 4 + 0] = t.x; v[i * 4 + 1] = t.y; v[i * 4 + 2] = t.z; v[i * 4 + 3] = t.w;
    }
    float s = 0.f;
#pragma unroll
    for (int i = 0; i < 16; i++) s += v[i];
#pragma unroll
    for (int o = 16; o > 0; o >>= 1) s += __shfl_xor_sync(0xffffffffu, s, o);
    float mu = s * (1.f / DMODEL);
    float q = 0.f;
#pragma unroll
    for (int i = 0; i < 16; i++) { float e = v[i] - mu; q = fmaf(e, e, q); }
#pragma unroll
    for (int o = 16; o > 0; o >>= 1) q += __shfl_xor_sync(0xffffffffu, q, o);
    float rs = rsqrtf(q * (1.f / DMODEL) + 1e-5f);
    float*  orow  = g_h   + (size_t)warp * DMODEL;
    __half* orow16= g_h16 + (size_t)warp * DMODEL;
#pragma unroll
    for (int i = 0; i < 4; i++) {
        int c = lane * 4 + i * 128;
        float4 gg = *reinterpret_cast<const float4*>(&gam[c]);
        float4 bb = *reinterpret_cast<const float4*>(&bet[c]);
        float4 o;
        o.x = (v[i*4+0] - mu) * rs * gg.x + bb.x;
        o.y = (v[i*4+1] - mu) * rs * gg.y + bb.y;
        o.z = (v[i*4+2] - mu) * rs * gg.z + bb.z;
        o.w = (v[i*4+3] - mu) * rs * gg.w + bb.w;
        *reinterpret_cast<float4*>(&orow[c]) = o;
        *reinterpret_cast<__half2*>(&orow16[c])     = __floats2half2_rn(o.x, o.y);
        *reinterpret_cast<__half2*>(&orow16[c + 2]) = __floats2half2_rn(o.z, o.w);
    }
}

// ---------------- mean pool, 2-phase ----------------
__global__ void pool1_kernel() {
    int b   = blockIdx.x;
    int seg = blockIdx.y;
    int c   = threadIdx.x;                 // 512 threads
    const float* p = g_h + ((size_t)(b * LSEQ + seg * (LSEQ / POOL_SEGS))) * DMODEL + c;
    float a0 = 0.f, a1 = 0.f, a2 = 0.f, a3 = 0.f;
    float a4 = 0.f, a5 = 0.f, a6 = 0.f, a7 = 0.f;
#pragma unroll 4
    for (int l = 0; l < LSEQ / POOL_SEGS; l += 8) {
        a0 += p[(l + 0) * DMODEL]; a1 += p[(l + 1) * DMODEL];
        a2 += p[(l + 2) * DMODEL]; a3 += p[(l + 3) * DMODEL];
        a4 += p[(l + 4) * DMODEL]; a5 += p[(l + 5) * DMODEL];
        a6 += p[(l + 6) * DMODEL]; a7 += p[(l + 7) * DMODEL];
    }
    g_poolp[(b * POOL_SEGS + seg) * DMODEL + c] =
        ((a0 + a1) + (a2 + a3)) + ((a4 + a5) + (a6 + a7));
}
__global__ void pool2_kernel() {
    int b = blockIdx.x;
    int c = threadIdx.x;
    float s = 0.f;
#pragma unroll
    for (int seg = 0; seg < POOL_SEGS; seg++)
        s += g_poolp[(b * POOL_SEGS + seg) * DMODEL + c];
    g_pool[b * DMODEL + c] = s * (1.f / LSEQ);
}

// ---------------- classifier head: warp per output, coalesced ----------------
__global__ __launch_bounds__(256) void head_kernel(
    const float* __restrict__ Wout, const float* __restrict__ bout,
    float* __restrict__ out)
{
    int wgl  = (blockIdx.x * blockDim.x + threadIdx.x) >> 5;
    int lane = threadIdx.x & 31;
    if (wgl >= BATCH * NCLASSES) return;
    int m = wgl / NCLASSES, n = wgl % NCLASSES;
    const float* p  = g_pool + m * DMODEL;
    const float* wr = Wout + (size_t)n * DMODEL;
    float s = 0.f;
#pragma unroll
    for (int i = 0; i < 4; i++) {
        int k = i * 128 + lane * 4;
        float4 a = *reinterpret_cast<const float4*>(p + k);
        float4 w = *reinterpret_cast<const float4*>(wr + k);
        s = fmaf(a.x, w.x, s); s = fmaf(a.y, w.y, s);
        s = fmaf(a.z, w.z, s); s = fmaf(a.w, w.w, s);
    }
#pragma unroll
    for (int o = 16; o > 0; o >>= 1)
        s += __shfl_xor_sync(0xffffffffu, s, o);
    if (lane == 0) out[wgl] = s + bout[n];
}

// ---------------- launcher ----------------
extern "C" void kernel_launch(void* const* d_in, const int* in_sizes, int n_in,
                              void* d_out, int out_size)
{
    const float* x      = (const float*)d_in[0];
    const float* Wp     = (const float*)d_in[1];
    const float* bp     = (const float*)d_in[2];
    const float* Wi     = (const float*)d_in[3];
    const float* conv_w = (const float*)d_in[4];
    const float* conv_b = (const float*)d_in[5];
    const float* Wx     = (const float*)d_in[6];
    const float* Wdt    = (const float*)d_in[7];
    const float* bdt    = (const float*)d_in[8];
    const float* A_log  = (const float*)d_in[9];
    const float* Dv     = (const float*)d_in[10];
    const float* Wo     = (const float*)d_in[11];
    const float* ln_g   = (const float*)d_in[12];
    const float* ln_b   = (const float*)d_in[13];
    const float* Wout   = (const float*)d_in[14];
    const float* bout   = (const float*)d_in[15];
    float* out = (float*)d_out;

    float *p_xz, *p_dbc, *p_delta, *p_gout;
    __half *p_w16, *p_x16, *p_h16, *p_xc16, *p_dbc16, *p_y16;
    cudaGetSymbolAddress((void**)&p_xz,    g_xz);
    cudaGetSymbolAddress((void**)&p_dbc,   g_dbc);
    cudaGetSymbolAddress((void**)&p_delta, g_delta);
    cudaGetSymbolAddress((void**)&p_gout,  g_gout);
    cudaGetSymbolAddress((void**)&p_w16,   g_w16);
    cudaGetSymbolAddress((void**)&p_x16,   g_x16);
    cudaGetSymbolAddress((void**)&p_h16,   g_h16);
    cudaGetSymbolAddress((void**)&p_xc16,  g_xc16);
    cudaGetSymbolAddress((void**)&p_dbc16, g_dbc16);
    cudaGetSymbolAddress((void**)&p_y16,   g_y16);

    cudaFuncSetAttribute(hgemm<1,false,true>, cudaFuncAttributeMaxDynamicSharedMemorySize, HGEMM_SMEM);
    cudaFuncSetAttribute(hgemm<0,true,false>, cudaFuncAttributeMaxDynamicSharedMemorySize, HGEMM_SMEM);
    cudaFuncSetAttribute(hgemm<0,true,true>,  cudaFuncAttributeMaxDynamicSharedMemorySize, HGEMM_SMEM);
    cudaFuncSetAttribute(hgemm<2,true,false>, cudaFuncAttributeMaxDynamicSharedMemorySize, HGEMM_SMEM);

    {
        int total = WP_SZ + WI_SZ + WX_SZ + WDT_SZ + WO_SZ + X16_SZ;
        wcvt_kernel<<<(total + 255) / 256, 256>>>(Wp, Wi, Wx, Wdt, Wo, x);
    }
    a2_kernel<<<(NLAYERS * DINNER * DSTATE + 255) / 256, 256>>>(A_log);

    hgemm<1,false,true><<<dim3(NTOK / 128, DMODEL / 128), 256, HGEMM_SMEM>>>(
        p_x16, NMELS, p_w16 + WP_OFF, nullptr, p_h16, DMODEL, DMODEL, NMELS, bp);

    for (int lyr = 0; lyr < NLAYERS; lyr++) {
        hgemm<0,true,false><<<dim3(NTOK / 128, (2 * DINNER) / 128), 256, HGEMM_SMEM>>>(
            p_h16, DMODEL, p_w16 + WI_OFF + (size_t)lyr * 2 * DINNER * DMODEL,
            p_xz, nullptr, 2 * DINNER, 2 * DINNER, DMODEL, nullptr);

        conv_kernel<<<(NTOK * DINNER / 4) / 256, 256>>>(
            conv_w + lyr * DINNER * DCONV, conv_b + lyr * DINNER);

        hgemm<0,true,true><<<dim3(NTOK / 128, 1), 256, HGEMM_SMEM>>>(
            p_xc16, DINNER, p_w16 + WX_OFF + (size_t)lyr * DBCW * DINNER,
            p_dbc, p_dbc16, DBCW, DBCW, DINNER, nullptr);

        hgemm<2,true,false><<<dim3(NTOK / 128, DINNER / 128), 256, HGEMM_SMEM>>>(
            p_dbc16, DBCW, p_w16 + WDT_OFF + (size_t)lyr * DINNER * DTRANK,
            p_delta, nullptr, DINNER, DINNER, DTRANK, bdt + lyr * DINNER);

        // scan v3: 8 batches x 32 channel-slices = 256 blocks
        scan_kernel<<<BATCH * 32, 256>>>(lyr, Dv + lyr * DINNER);

        hgemm<0,true,false><<<dim3(NTOK / 128, DMODEL / 128), 256, HGEMM_SMEM>>>(
            p_y16, DINNER, p_w16 + WO_OFF + (size_t)lyr * DMODEL * DINNER,
            p_gout, nullptr, DMODEL, DMODEL, DINNER, nullptr);

        ln_kernel<<<NTOK * 32 / 256, 256>>>(ln_g + lyr * DMODEL, ln_b + lyr * DMODEL);
    }

    pool1_kernel<<<dim3(BATCH, POOL_SEGS), DMODEL>>>();
    pool2_kernel<<<BATCH, DMODEL>>>();
    head_kernel<<<(BATCH * NCLASSES * 32 + 255) / 256, 256>>>(Wout, bout, out);
}